// round 10
// baseline (speedup 1.0000x reference)
#include <cuda_runtime.h>
#include <cuda_fp16.h>
#include <math.h>
#include <stdint.h>

// Problem constants
#define BATCH 16
#define TT    1024
#define DMODEL 256
#define NHEAD 4
#define DKEY  64
#define HDIM  256
#define MROWS (BATCH*TT)   // 16384
#define NB    128          // keys per block

// Q pre-scale: (1/sqrt(64)) * log2(e)  -> scores come out in log2 domain
#define QSCALE 0.1803368801111204f

// ---------------- device scratch ----------------
__device__ uint32_t g_qi16[MROWS * DMODEL / 2];
__device__ uint32_t g_ki16[MROWS * DMODEL / 2];
__device__ uint32_t g_vi16[MROWS * DMODEL / 2];
__device__ uint32_t g_wq [HDIM * DMODEL / 2];
__device__ uint32_t g_wk [HDIM * DMODEL / 2];
__device__ uint32_t g_wvh[DKEY * DMODEL / 2];
__device__ uint32_t g_wvl[DKEY * DMODEL / 2];
__device__ uint32_t g_wo [HDIM * DMODEL / 2];
__device__ uint32_t g_q16[MROWS * HDIM / 2];
__device__ uint32_t g_k16[MROWS * HDIM / 2];
__device__ uint32_t g_v16[MROWS * DKEY / 2];
__device__ uint32_t g_ao16[MROWS * HDIM / 2];

// =============== helpers ===============
__device__ __forceinline__ uint32_t pack_f16x2(float lo, float hi) {
    uint32_t w;
    asm("cvt.rn.f16x2.f32 %0, %1, %2;" : "=r"(w) : "f"(hi), "f"(lo));
    return w;
}
__device__ __forceinline__ float f16_lo_f32(uint32_t w) {
    float f;
    asm("{.reg .b16 l,h; mov.b32 {l,h}, %1; cvt.f32.f16 %0, l;}" : "=f"(f) : "r"(w));
    return f;
}
__device__ __forceinline__ float f16_hi_f32(uint32_t w) {
    float f;
    asm("{.reg .b16 l,h; mov.b32 {l,h}, %1; cvt.f32.f16 %0, h;}" : "=f"(f) : "r"(w));
    return f;
}
__device__ __forceinline__ float ex2f(float x) {
    float y;
    asm("ex2.approx.ftz.f32 %0, %1;" : "=f"(y) : "f"(x));
    return y;
}
__device__ __forceinline__ void mma_f16(float* c, const uint32_t* a, const uint32_t* b) {
    asm volatile(
        "mma.sync.aligned.m16n8k16.row.col.f32.f16.f16.f32 "
        "{%0,%1,%2,%3}, {%4,%5,%6,%7}, {%8,%9}, {%0,%1,%2,%3};"
        : "+f"(c[0]), "+f"(c[1]), "+f"(c[2]), "+f"(c[3])
        : "r"(a[0]), "r"(a[1]), "r"(a[2]), "r"(a[3]), "r"(b[0]), "r"(b[1]));
}
__device__ __forceinline__ void ldmatrix_x4(uint32_t* r, uint32_t addr) {
    asm volatile("ldmatrix.sync.aligned.m8n8.x4.shared.b16 {%0,%1,%2,%3}, [%4];"
        : "=r"(r[0]), "=r"(r[1]), "=r"(r[2]), "=r"(r[3]) : "r"(addr));
}
__device__ __forceinline__ void ldmatrix_x4_t(uint32_t* r, uint32_t addr) {
    asm volatile("ldmatrix.sync.aligned.m8n8.x4.trans.shared.b16 {%0,%1,%2,%3}, [%4];"
        : "=r"(r[0]), "=r"(r[1]), "=r"(r[2]), "=r"(r[3]) : "r"(addr));
}
__device__ __forceinline__ void cp_async16(uint32_t dst, const void* src) {
    asm volatile("cp.async.cg.shared.global [%0], [%1], 16;" :: "r"(dst), "l"(src) : "memory");
}
__device__ __forceinline__ void cp_commit() { asm volatile("cp.async.commit_group;" ::: "memory"); }
template<int W> __device__ __forceinline__ void cp_wait() {
    asm volatile("cp.async.wait_group %0;" :: "n"(W) : "memory");
}

// ======================================================================
// prep: ONE launch. Blocks [0,1024): input f32->f16. Blocks [1024,1440):
// weight transpose/convert (Wq 128 | Wk 128 | Wv 32 (+lo) | Wo 128 blocks).
// ======================================================================
__global__ void prep(const float* __restrict__ q, const float* __restrict__ k,
                     const float* __restrict__ v,
                     const float* __restrict__ Wq, const float* __restrict__ Wk,
                     const float* __restrict__ Wv, const float* __restrict__ Wo,
                     uint32_t* __restrict__ q16, uint32_t* __restrict__ k16,
                     uint32_t* __restrict__ v16,
                     uint32_t* __restrict__ wq, uint32_t* __restrict__ wk,
                     uint32_t* __restrict__ wvh, uint32_t* __restrict__ wvl,
                     uint32_t* __restrict__ wo) {
    const int bx = blockIdx.x;
    if (bx < 1024) {
        const int n = MROWS * DMODEL / 4;
        for (int i = bx * 256 + threadIdx.x; i < n; i += 1024 * 256) {
            float4 a = ((const float4*)q)[i];
            ((uint2*)q16)[i] = make_uint2(pack_f16x2(a.x, a.y), pack_f16x2(a.z, a.w));
            a = ((const float4*)k)[i];
            ((uint2*)k16)[i] = make_uint2(pack_f16x2(a.x, a.y), pack_f16x2(a.z, a.w));
            a = ((const float4*)v)[i];
            ((uint2*)v16)[i] = make_uint2(pack_f16x2(a.x, a.y), pack_f16x2(a.z, a.w));
        }
        return;
    }
    const int wb = bx - 1024;   // 0..415
    int which, setbase;
    if      (wb < 128) { which = 0; setbase = 0;   }
    else if (wb < 256) { which = 1; setbase = 128; }
    else if (wb < 288) { which = 2; setbase = 256; }
    else               { which = 3; setbase = 288; }
    const int N = (which == 2) ? 64 : 256;
    const int t = (wb - setbase) * 256 + threadIdx.x;
    if (t >= N * 128) return;
    const float* W = (which == 0) ? Wq : (which == 1) ? Wk : (which == 2) ? Wv : Wo;
    uint32_t* Wt   = (which == 0) ? wq : (which == 1) ? wk : (which == 2) ? wvh : wo;
    const int n = t % N;
    const int kp = t / N;
    const float w0 = W[(size_t)(2 * kp) * N + n];
    const float w1 = W[(size_t)(2 * kp + 1) * N + n];
    const uint32_t hw = pack_f16x2(w0, w1);
    Wt[(size_t)n * 128 + kp] = hw;
    if (which == 2)
        wvl[(size_t)n * 128 + kp] = pack_f16x2(w0 - f16_lo_f32(hw), w1 - f16_hi_f32(hw));
}

// ======================================================================
// Fused QKV projection GEMM, ONE launch, grid (4, 128, 3).
// z=0: Q (N=256, scale=QSCALE); z=1: K (N=256); z=2: V (N=64, W-compensated,
//      only blockIdx.x==0 active). f16-packed output everywhere.
// BM=128, BN=64, BK=64, 256 threads, cp.async double-buffered.
// ======================================================================
#define G_WOFF  (128*36)
#define G_WLOFF (G_WOFF + 64*36)
#define G_BUF   (G_WLOFF + 64*36)       // u32 per buffer (incl. W-lo space)

__global__ void __launch_bounds__(256) gemm_qkv(
        const uint32_t* __restrict__ qi, const uint32_t* __restrict__ ki,
        const uint32_t* __restrict__ vi,
        const uint32_t* __restrict__ wq, const uint32_t* __restrict__ wk,
        const uint32_t* __restrict__ wvh, const uint32_t* __restrict__ wvl,
        const float* __restrict__ bq, const float* __restrict__ bk,
        const float* __restrict__ bv,
        uint32_t* __restrict__ q16, uint32_t* __restrict__ k16,
        uint32_t* __restrict__ v16) {
    const int z = blockIdx.z;
    const bool wcomp = (z == 2);
    if (wcomp && blockIdx.x != 0) return;

    const uint32_t* A16 = (z == 0) ? qi : (z == 1) ? ki : vi;
    const uint32_t* Wt  = (z == 0) ? wq : (z == 1) ? wk : wvh;
    const float* bias   = (z == 0) ? bq : (z == 1) ? bk : bv;
    uint32_t* C16       = (z == 0) ? q16 : (z == 1) ? k16 : v16;
    const int N         = wcomp ? 64 : 256;
    const float scale   = (z == 0) ? QSCALE : 1.0f;

    extern __shared__ __align__(16) uint32_t sm[];
    const uint32_t ub = (uint32_t)__cvta_generic_to_shared(sm);

    const int tid = threadIdx.x;
    const int wid = tid >> 5;
    const int lane = tid & 31;
    const int g = lane >> 2, q4 = lane & 3;
    const int rowBase = blockIdx.y * 128;
    const int n0 = blockIdx.x * 64;
    const int m0 = wid * 16;

    auto load_tiles = [&](int kb, int bufsel) {
        const uint32_t d0 = ub + (uint32_t)bufsel * G_BUF * 4;
        const int ar = tid >> 1, half = (tid & 1) * 16;
        const uint32_t* asrc = A16 + (size_t)(rowBase + ar) * 128 + kb * 32 + half;
        const uint32_t adst = d0 + (uint32_t)(ar * 36 + half) * 4;
#pragma unroll
        for (int u = 0; u < 4; u++) cp_async16(adst + u * 16, asrc + u * 4);
#pragma unroll
        for (int c = 0; c < 2; c++) {
            const int cc = tid + c * 256;
            const int wr = cc >> 3, off = (cc & 7) * 4;
            cp_async16(d0 + (uint32_t)(G_WOFF + wr * 36 + off) * 4,
                       Wt + (size_t)(n0 + wr) * 128 + kb * 32 + off);
            if (wcomp)
                cp_async16(d0 + (uint32_t)(G_WLOFF + wr * 36 + off) * 4,
                           wvl + (size_t)(n0 + wr) * 128 + kb * 32 + off);
        }
    };

    float O[8][4];
#pragma unroll
    for (int n = 0; n < 8; n++)
#pragma unroll
        for (int r = 0; r < 4; r++) O[n][r] = 0.f;

    load_tiles(0, 0);
    cp_commit();

    for (int kb = 0; kb < 4; kb++) {
        if (kb < 3) { load_tiles(kb + 1, (kb + 1) & 1); cp_commit(); cp_wait<1>(); }
        else        { cp_wait<0>(); }
        __syncthreads();

        const uint32_t bb = ub + (uint32_t)(kb & 1) * G_BUF * 4;
        const uint32_t aBase = bb + (uint32_t)(m0 + (lane & 15)) * 144 + ((lane >> 4) & 1) * 16;
        const uint32_t bBase = bb + G_WOFF * 4 + (uint32_t)(lane & 7) * 144 + ((lane >> 3) & 3) * 16;

#pragma unroll
        for (int kcp = 0; kcp < 2; kcp++) {
            uint32_t Aa[4], Ab[4];
            ldmatrix_x4(Aa, aBase + (2 * kcp) * 32);
            ldmatrix_x4(Ab, aBase + (2 * kcp + 1) * 32);
#pragma unroll
            for (int nt = 0; nt < 8; nt++) {
                uint32_t Bf[4];
                ldmatrix_x4(Bf, bBase + (uint32_t)nt * 8 * 144 + kcp * 64);
                mma_f16(O[nt], Aa, Bf);
                mma_f16(O[nt], Ab, Bf + 2);
                if (wcomp) {
                    uint32_t Bl[4];
                    ldmatrix_x4(Bl, bBase + (uint32_t)(G_WLOFF - G_WOFF) * 4 +
                                    (uint32_t)nt * 8 * 144 + kcp * 64);
                    mma_f16(O[nt], Aa, Bl);
                    mma_f16(O[nt], Ab, Bl + 2);
                }
            }
        }
        __syncthreads();
    }

    // ---- epilogue: f16 packed out ----
    const int r0 = rowBase + m0 + g;
#pragma unroll
    for (int nt = 0; nt < 8; nt++) {
        const int cg = n0 + nt * 8 + 2 * q4;
        const float b0 = bias[cg], b1 = bias[cg + 1];
        const float c0 = (O[nt][0] + b0) * scale, c1 = (O[nt][1] + b1) * scale;
        const float c2 = (O[nt][2] + b0) * scale, c3 = (O[nt][3] + b1) * scale;
        const int cu = (n0 >> 1) + nt * 4 + q4;
        C16[(size_t)r0 * (N / 2) + cu] = pack_f16x2(c0, c1);
        C16[(size_t)(r0 + 8) * (N / 2) + cu] = pack_f16x2(c2, c3);
    }
}

// ======================================================================
// Output projection GEMM: out = AO(16384 x 256) @ Wo + bo, f32 out.
// ======================================================================
#define GO_WOFF (128*36)
#define GO_BUF  (GO_WOFF + 64*36)

__global__ void __launch_bounds__(256) gemm_o(
        const uint32_t* __restrict__ A16, const uint32_t* __restrict__ Wt,
        const float* __restrict__ bias, float* __restrict__ Cf) {
    extern __shared__ __align__(16) uint32_t sm[];
    const uint32_t ub = (uint32_t)__cvta_generic_to_shared(sm);

    const int tid = threadIdx.x;
    const int wid = tid >> 5;
    const int lane = tid & 31;
    const int g = lane >> 2, q4 = lane & 3;
    const int rowBase = blockIdx.y * 128;
    const int n0 = blockIdx.x * 64;
    const int m0 = wid * 16;

    auto load_tiles = [&](int kb, int bufsel) {
        const uint32_t d0 = ub + (uint32_t)bufsel * GO_BUF * 4;
        const int ar = tid >> 1, half = (tid & 1) * 16;
        const uint32_t* asrc = A16 + (size_t)(rowBase + ar) * 128 + kb * 32 + half;
        const uint32_t adst = d0 + (uint32_t)(ar * 36 + half) * 4;
#pragma unroll
        for (int u = 0; u < 4; u++) cp_async16(adst + u * 16, asrc + u * 4);
#pragma unroll
        for (int c = 0; c < 2; c++) {
            const int cc = tid + c * 256;
            const int wr = cc >> 3, off = (cc & 7) * 4;
            cp_async16(d0 + (uint32_t)(GO_WOFF + wr * 36 + off) * 4,
                       Wt + (size_t)(n0 + wr) * 128 + kb * 32 + off);
        }
    };

    float O[8][4];
#pragma unroll
    for (int n = 0; n < 8; n++)
#pragma unroll
        for (int r = 0; r < 4; r++) O[n][r] = 0.f;

    load_tiles(0, 0);
    cp_commit();

    for (int kb = 0; kb < 4; kb++) {
        if (kb < 3) { load_tiles(kb + 1, (kb + 1) & 1); cp_commit(); cp_wait<1>(); }
        else        { cp_wait<0>(); }
        __syncthreads();

        const uint32_t bb = ub + (uint32_t)(kb & 1) * GO_BUF * 4;
        const uint32_t aBase = bb + (uint32_t)(m0 + (lane & 15)) * 144 + ((lane >> 4) & 1) * 16;
        const uint32_t bBase = bb + GO_WOFF * 4 + (uint32_t)(lane & 7) * 144 + ((lane >> 3) & 3) * 16;

#pragma unroll
        for (int kcp = 0; kcp < 2; kcp++) {
            uint32_t Aa[4], Ab[4];
            ldmatrix_x4(Aa, aBase + (2 * kcp) * 32);
            ldmatrix_x4(Ab, aBase + (2 * kcp + 1) * 32);
#pragma unroll
            for (int nt = 0; nt < 8; nt++) {
                uint32_t Bf[4];
                ldmatrix_x4(Bf, bBase + (uint32_t)nt * 8 * 144 + kcp * 64);
                mma_f16(O[nt], Aa, Bf);
                mma_f16(O[nt], Ab, Bf + 2);
            }
        }
        __syncthreads();
    }

    const int r0 = rowBase + m0 + g;
#pragma unroll
    for (int nt = 0; nt < 8; nt++) {
        const int cg = n0 + nt * 8 + 2 * q4;
        const float b0 = bias[cg], b1 = bias[cg + 1];
        *(float2*)&Cf[(size_t)r0 * 256 + cg] = make_float2(O[nt][0] + b0, O[nt][1] + b1);
        *(float2*)&Cf[(size_t)(r0 + 8) * 256 + cg] = make_float2(O[nt][2] + b0, O[nt][3] + b1);
    }
}

// ======================================================================
// fp16 flash attention (R8-proven: cp.async dbl-buf, ldmatrix.trans V,
// ones-column row sums on the tensor pipe, log2-domain exp).
// ======================================================================
#define AT_VOFF (128*36)
#define AT_BUF  (2*128*36)

__global__ void __launch_bounds__(256) attn16(
        const uint32_t* __restrict__ gq, const uint32_t* __restrict__ gk,
        const uint32_t* __restrict__ gv, uint32_t* __restrict__ ao) {
    extern __shared__ __align__(16) uint32_t sm[];
    const uint32_t ub = (uint32_t)__cvta_generic_to_shared(sm);

    const int tid = threadIdx.x;
    const int wid = tid >> 5;
    const int lane = tid & 31;
    const int g = lane >> 2, q4 = lane & 3;

    const int bh = blockIdx.y;
    const int b = bh >> 2, h = bh & 3;
    const int q0 = blockIdx.x * 128;
    const int m0 = q0 + wid * 16;

    // ones-pad init (V u32 cols 32..35, both buffers)
    {
        const int buf = tid >> 7, row = tid & 127;
        uint4 ones = make_uint4(0x3C003C00u, 0x3C003C00u, 0x3C003C00u, 0x3C003C00u);
        *(uint4*)&sm[buf * AT_BUF + AT_VOFF + row * 36 + 32] = ones;
    }

    // Q fragments (resident; scaled by QSCALE in projection)
    uint32_t Qf[4][4];
    {
        const uint32_t* qp = gq + (size_t)(b*TT + m0 + g) * 128 + h * 32;
#pragma unroll
        for (int kc = 0; kc < 4; kc++) {
            const int du = kc * 8 + q4;
            Qf[kc][0] = qp[du];         Qf[kc][1] = qp[8*128 + du];
            Qf[kc][2] = qp[du + 4];     Qf[kc][3] = qp[8*128 + du + 4];
        }
    }

    const int kn = tid >> 1;
    const int half = (tid & 1) * 16;

    auto load_kv = [&](int it, int bufsel) {
        const uint32_t d0 = ub + (uint32_t)bufsel * AT_BUF * 4;
        const int row = b * TT + it * NB + kn;
        const uint32_t* ks = gk + (size_t)row * 128 + h * 32 + half;
        const uint32_t kd = d0 + (uint32_t)(kn * 36 + half) * 4;
#pragma unroll
        for (int u = 0; u < 4; u++) cp_async16(kd + u * 16, ks + u * 4);
        const uint32_t* vs = gv + (size_t)row * 32 + half;
        const uint32_t vd = d0 + (uint32_t)(AT_VOFF + kn * 36 + half) * 4;
#pragma unroll
        for (int u = 0; u < 4; u++) cp_async16(vd + u * 16, vs + u * 4);
    };

    float O[8][4];
#pragma unroll
    for (int n = 0; n < 8; n++)
#pragma unroll
        for (int r = 0; r < 4; r++) O[n][r] = 0.f;
    float Osum[4] = {0.f, 0.f, 0.f, 0.f};

    const int vLaneRow = (lane & 7) + 8 * ((lane >> 3) & 3);

    load_kv(0, 0);
    cp_commit();

    for (int it = 0; it < TT / NB; it++) {
        if (it + 1 < TT / NB) { load_kv(it + 1, (it + 1) & 1); cp_commit(); cp_wait<1>(); }
        else                  { cp_wait<0>(); }
        __syncthreads();

        const uint32_t bb = ub + (uint32_t)(it & 1) * AT_BUF * 4;
        const uint32_t kBase = bb + (uint32_t)(lane & 7) * 144 + ((lane >> 3) & 3) * 16;
        const uint32_t vBase = bb + AT_VOFF * 4 + (uint32_t)vLaneRow * 144;

#pragma unroll
        for (int sub = 0; sub < 2; sub++) {
            float S[8][4];
#pragma unroll
            for (int jj = 0; jj < 8; jj++) {
#pragma unroll
                for (int r = 0; r < 4; r++) S[jj][r] = 0.f;
                const uint32_t rowoff = (uint32_t)(sub*64 + jj*8) * 144;
#pragma unroll
                for (int kcp = 0; kcp < 2; kcp++) {
                    uint32_t Bf[4];
                    ldmatrix_x4(Bf, kBase + rowoff + kcp * 64);
                    mma_f16(S[jj], Qf[2*kcp],     Bf);
                    mma_f16(S[jj], Qf[2*kcp + 1], Bf + 2);
                }
            }
#pragma unroll
            for (int jj = 0; jj < 8; jj++) {
                S[jj][0] = ex2f(S[jj][0]);
                S[jj][1] = ex2f(S[jj][1]);
                S[jj][2] = ex2f(S[jj][2]);
                S[jj][3] = ex2f(S[jj][3]);
            }
#pragma unroll
            for (int kc2p = 0; kc2p < 2; kc2p++) {
                uint32_t PhA[4], PhB[4];
                {
                    const float* t0 = S[4*kc2p + 0];
                    const float* t1 = S[4*kc2p + 1];
                    PhA[0] = pack_f16x2(t0[0], t0[1]);
                    PhA[1] = pack_f16x2(t0[2], t0[3]);
                    PhA[2] = pack_f16x2(t1[0], t1[1]);
                    PhA[3] = pack_f16x2(t1[2], t1[3]);
                    const float* t2 = S[4*kc2p + 2];
                    const float* t3 = S[4*kc2p + 3];
                    PhB[0] = pack_f16x2(t2[0], t2[1]);
                    PhB[1] = pack_f16x2(t2[2], t2[3]);
                    PhB[2] = pack_f16x2(t3[0], t3[1]);
                    PhB[3] = pack_f16x2(t3[2], t3[3]);
                }
                const uint32_t koff = (uint32_t)(sub*64 + kc2p*32) * 144;
#pragma unroll
                for (int nt = 0; nt < 8; nt++) {
                    uint32_t Vf[4];
                    ldmatrix_x4_t(Vf, vBase + koff + (uint32_t)nt * 16);
                    mma_f16(O[nt], PhA, Vf);
                    mma_f16(O[nt], PhB, Vf + 2);
                }
                {
                    uint32_t Vf[4];
                    ldmatrix_x4_t(Vf, vBase + koff + 8 * 16);
                    mma_f16(Osum, PhA, Vf);
                    mma_f16(Osum, PhB, Vf + 2);
                }
            }
        }
        __syncthreads();
    }

    const float inv0 = 1.f / Osum[0];
    const float inv1 = 1.f / Osum[2];

    uint32_t* dh = ao + (size_t)(b*TT + m0 + g) * 128 + h * 32;
#pragma unroll
    for (int nt = 0; nt < 8; nt++) {
        const int cu = nt * 4 + q4;
        dh[cu]         = pack_f16x2(O[nt][0] * inv0, O[nt][1] * inv0);
        dh[8*128 + cu] = pack_f16x2(O[nt][2] * inv1, O[nt][3] * inv1);
    }
}

// ---------------- launch ----------------
extern "C" void kernel_launch(void* const* d_in, const int* in_sizes, int n_in,
                              void* d_out, int out_size) {
    (void)in_sizes; (void)n_in; (void)out_size;
    const float* query = (const float*)d_in[0];
    const float* key   = (const float*)d_in[1];
    const float* value = (const float*)d_in[2];
    const float* Wq    = (const float*)d_in[3];
    const float* bq    = (const float*)d_in[4];
    const float* Wk    = (const float*)d_in[5];
    const float* bk    = (const float*)d_in[6];
    const float* Wv    = (const float*)d_in[7];
    const float* bv    = (const float*)d_in[8];
    const float* Wo    = (const float*)d_in[9];
    const float* bo    = (const float*)d_in[10];
    float* out = (float*)d_out;

    uint32_t *qi_, *ki_, *vi_, *wq_, *wk_, *wvh_, *wvl_, *wo_;
    uint32_t *q16_, *k16_, *v16_, *ao_;
    cudaGetSymbolAddress((void**)&qi_,  g_qi16);
    cudaGetSymbolAddress((void**)&ki_,  g_ki16);
    cudaGetSymbolAddress((void**)&vi_,  g_vi16);
    cudaGetSymbolAddress((void**)&wq_,  g_wq);
    cudaGetSymbolAddress((void**)&wk_,  g_wk);
    cudaGetSymbolAddress((void**)&wvh_, g_wvh);
    cudaGetSymbolAddress((void**)&wvl_, g_wvl);
    cudaGetSymbolAddress((void**)&wo_,  g_wo);
    cudaGetSymbolAddress((void**)&q16_, g_q16);
    cudaGetSymbolAddress((void**)&k16_, g_k16);
    cudaGetSymbolAddress((void**)&v16_, g_v16);
    cudaGetSymbolAddress((void**)&ao_,  g_ao16);

    const int sm_qkv = 2 * G_BUF * 4;    // 73728
    const int sm_o   = 2 * GO_BUF * 4;   // 55296
    const int sm_at  = 2 * AT_BUF * 4;   // 73728
    cudaFuncSetAttribute(gemm_qkv, cudaFuncAttributeMaxDynamicSharedMemorySize, sm_qkv);
    cudaFuncSetAttribute(gemm_o,   cudaFuncAttributeMaxDynamicSharedMemorySize, sm_o);
    cudaFuncSetAttribute(attn16,   cudaFuncAttributeMaxDynamicSharedMemorySize, sm_at);

    // 1) prepass (inputs + all weights, one launch)
    prep<<<1440, 256>>>(query, key, value, Wq, Wk, Wv, Wo,
                        qi_, ki_, vi_, wq_, wk_, wvh_, wvl_, wo_);
    // 2) fused Q/K/V projections (one launch; V plane overlaps QK)
    gemm_qkv<<<dim3(4, 128, 3), 256, sm_qkv>>>(qi_, ki_, vi_, wq_, wk_, wvh_, wvl_,
                                               bq, bk, bv, q16_, k16_, v16_);
    // 3) attention
    attn16<<<dim3(TT / 128, BATCH * NHEAD), 256, sm_at>>>(q16_, k16_, v16_, ao_);
    // 4) output projection
    gemm_o<<<dim3(4, 128), 256, sm_o>>>(ao_, wo_, bo, out);
}

// round 11
// speedup vs baseline: 1.0128x; 1.0128x over previous
#include <cuda_runtime.h>
#include <cuda_fp16.h>
#include <math.h>
#include <stdint.h>

// Problem constants
#define BATCH 16
#define TT    1024
#define DMODEL 256
#define NHEAD 4
#define DKEY  64
#define HDIM  256
#define MROWS (BATCH*TT)   // 16384
#define NB    128          // keys per block

// Q pre-scale: (1/sqrt(64)) * log2(e)  -> scores come out in log2 domain
#define QSCALE 0.1803368801111204f

// ---------------- device scratch ----------------
__device__ uint32_t g_qi16[MROWS * DMODEL / 2];
__device__ uint32_t g_ki16[MROWS * DMODEL / 2];
__device__ uint32_t g_vi16[MROWS * DMODEL / 2];
__device__ uint32_t g_wq [HDIM * DMODEL / 2];
__device__ uint32_t g_wk [HDIM * DMODEL / 2];
__device__ uint32_t g_wvh[DKEY * DMODEL / 2];
__device__ uint32_t g_wvl[DKEY * DMODEL / 2];
__device__ uint32_t g_wo [HDIM * DMODEL / 2];
__device__ uint32_t g_q16[MROWS * HDIM / 2];
__device__ uint32_t g_k16[MROWS * HDIM / 2];
__device__ uint32_t g_v16[MROWS * DKEY / 2];
__device__ uint32_t g_ao16[MROWS * HDIM / 2];

// =============== helpers ===============
__device__ __forceinline__ uint32_t pack_f16x2(float lo, float hi) {
    uint32_t w;
    asm("cvt.rn.f16x2.f32 %0, %1, %2;" : "=r"(w) : "f"(hi), "f"(lo));
    return w;
}
__device__ __forceinline__ float f16_lo_f32(uint32_t w) {
    float f;
    asm("{.reg .b16 l,h; mov.b32 {l,h}, %1; cvt.f32.f16 %0, l;}" : "=f"(f) : "r"(w));
    return f;
}
__device__ __forceinline__ float f16_hi_f32(uint32_t w) {
    float f;
    asm("{.reg .b16 l,h; mov.b32 {l,h}, %1; cvt.f32.f16 %0, h;}" : "=f"(f) : "r"(w));
    return f;
}
__device__ __forceinline__ float ex2f(float x) {
    float y;
    asm("ex2.approx.ftz.f32 %0, %1;" : "=f"(y) : "f"(x));
    return y;
}
__device__ __forceinline__ void mma_f16(float* c, const uint32_t* a, const uint32_t* b) {
    asm volatile(
        "mma.sync.aligned.m16n8k16.row.col.f32.f16.f16.f32 "
        "{%0,%1,%2,%3}, {%4,%5,%6,%7}, {%8,%9}, {%0,%1,%2,%3};"
        : "+f"(c[0]), "+f"(c[1]), "+f"(c[2]), "+f"(c[3])
        : "r"(a[0]), "r"(a[1]), "r"(a[2]), "r"(a[3]), "r"(b[0]), "r"(b[1]));
}
__device__ __forceinline__ void ldmatrix_x4(uint32_t* r, uint32_t addr) {
    asm volatile("ldmatrix.sync.aligned.m8n8.x4.shared.b16 {%0,%1,%2,%3}, [%4];"
        : "=r"(r[0]), "=r"(r[1]), "=r"(r[2]), "=r"(r[3]) : "r"(addr));
}
__device__ __forceinline__ void ldmatrix_x4_t(uint32_t* r, uint32_t addr) {
    asm volatile("ldmatrix.sync.aligned.m8n8.x4.trans.shared.b16 {%0,%1,%2,%3}, [%4];"
        : "=r"(r[0]), "=r"(r[1]), "=r"(r[2]), "=r"(r[3]) : "r"(addr));
}
__device__ __forceinline__ void cp_async16(uint32_t dst, const void* src) {
    asm volatile("cp.async.cg.shared.global [%0], [%1], 16;" :: "r"(dst), "l"(src) : "memory");
}
__device__ __forceinline__ void cp_commit() { asm volatile("cp.async.commit_group;" ::: "memory"); }
template<int W> __device__ __forceinline__ void cp_wait() {
    asm volatile("cp.async.wait_group %0;" :: "n"(W) : "memory");
}

// ======================================================================
// prep: ONE launch. Blocks [0,1024): input f32->f16. Blocks [1024,1440):
// weight transpose/convert (Wq 128 | Wk 128 | Wv 32 (+lo) | Wo 128 blocks).
// ======================================================================
__global__ void prep(const float* __restrict__ q, const float* __restrict__ k,
                     const float* __restrict__ v,
                     const float* __restrict__ Wq, const float* __restrict__ Wk,
                     const float* __restrict__ Wv, const float* __restrict__ Wo,
                     uint32_t* __restrict__ q16, uint32_t* __restrict__ k16,
                     uint32_t* __restrict__ v16,
                     uint32_t* __restrict__ wq, uint32_t* __restrict__ wk,
                     uint32_t* __restrict__ wvh, uint32_t* __restrict__ wvl,
                     uint32_t* __restrict__ wo) {
    const int bx = blockIdx.x;
    if (bx < 1024) {
        const int n = MROWS * DMODEL / 4;
        for (int i = bx * 256 + threadIdx.x; i < n; i += 1024 * 256) {
            float4 a = ((const float4*)q)[i];
            ((uint2*)q16)[i] = make_uint2(pack_f16x2(a.x, a.y), pack_f16x2(a.z, a.w));
            a = ((const float4*)k)[i];
            ((uint2*)k16)[i] = make_uint2(pack_f16x2(a.x, a.y), pack_f16x2(a.z, a.w));
            a = ((const float4*)v)[i];
            ((uint2*)v16)[i] = make_uint2(pack_f16x2(a.x, a.y), pack_f16x2(a.z, a.w));
        }
        return;
    }
    const int wb = bx - 1024;   // 0..415
    int which, setbase;
    if      (wb < 128) { which = 0; setbase = 0;   }
    else if (wb < 256) { which = 1; setbase = 128; }
    else if (wb < 288) { which = 2; setbase = 256; }
    else               { which = 3; setbase = 288; }
    const int N = (which == 2) ? 64 : 256;
    const int t = (wb - setbase) * 256 + threadIdx.x;
    if (t >= N * 128) return;
    const float* W = (which == 0) ? Wq : (which == 1) ? Wk : (which == 2) ? Wv : Wo;
    uint32_t* Wt   = (which == 0) ? wq : (which == 1) ? wk : (which == 2) ? wvh : wo;
    const int n = t % N;
    const int kp = t / N;
    const float w0 = W[(size_t)(2 * kp) * N + n];
    const float w1 = W[(size_t)(2 * kp + 1) * N + n];
    const uint32_t hw = pack_f16x2(w0, w1);
    Wt[(size_t)n * 128 + kp] = hw;
    if (which == 2)
        wvl[(size_t)n * 128 + kp] = pack_f16x2(w0 - f16_lo_f32(hw), w1 - f16_hi_f32(hw));
}

// ======================================================================
// Fused QKV projection GEMM, BM=64, 128 threads (4 warps, m16 x n64 each),
// grid (4, 256, 3). z=0: Q (scale=QSCALE); z=1: K; z=2: V (N=64, W-comp,
// only x==0 active). cp.async double-buffered. f16-packed output.
// smem u32/buffer: A[64][36] | W[64][36] | Wlo[64][36]
// ======================================================================
#define G_AT    (64*36)
#define G_WOFF  G_AT
#define G_WLOFF (G_WOFF + 64*36)
#define G_BUF   (G_WLOFF + 64*36)       // 6912 u32 per buffer

__global__ void __launch_bounds__(128) gemm_qkv(
        const uint32_t* __restrict__ qi, const uint32_t* __restrict__ ki,
        const uint32_t* __restrict__ vi,
        const uint32_t* __restrict__ wq, const uint32_t* __restrict__ wk,
        const uint32_t* __restrict__ wvh, const uint32_t* __restrict__ wvl,
        const float* __restrict__ bq, const float* __restrict__ bk,
        const float* __restrict__ bv,
        uint32_t* __restrict__ q16, uint32_t* __restrict__ k16,
        uint32_t* __restrict__ v16) {
    const int z = blockIdx.z;
    const bool wcomp = (z == 2);
    if (wcomp && blockIdx.x != 0) return;

    const uint32_t* A16 = (z == 0) ? qi : (z == 1) ? ki : vi;
    const uint32_t* Wt  = (z == 0) ? wq : (z == 1) ? wk : wvh;
    const float* bias   = (z == 0) ? bq : (z == 1) ? bk : bv;
    uint32_t* C16       = (z == 0) ? q16 : (z == 1) ? k16 : v16;
    const int N         = wcomp ? 64 : 256;
    const float scale   = (z == 0) ? QSCALE : 1.0f;

    extern __shared__ __align__(16) uint32_t sm[];
    const uint32_t ub = (uint32_t)__cvta_generic_to_shared(sm);

    const int tid = threadIdx.x;
    const int wid = tid >> 5;
    const int lane = tid & 31;
    const int g = lane >> 2, q4 = lane & 3;
    const int rowBase = blockIdx.y * 64;
    const int n0 = blockIdx.x * 64;
    const int m0 = wid * 16;

    auto load_tiles = [&](int kb, int bufsel) {
        const uint32_t d0 = ub + (uint32_t)bufsel * G_BUF * 4;
        // A: 64 rows x 32 u32
        const int ar = tid >> 1, half = (tid & 1) * 16;
        const uint32_t* asrc = A16 + (size_t)(rowBase + ar) * 128 + kb * 32 + half;
        const uint32_t adst = d0 + (uint32_t)(ar * 36 + half) * 4;
#pragma unroll
        for (int u = 0; u < 4; u++) cp_async16(adst + u * 16, asrc + u * 4);
        // W: 64 rows x 32 u32 (8 cp16 per row, 512 total, 4 per thread)
#pragma unroll
        for (int c = 0; c < 4; c++) {
            const int cc = c * 128 + tid;
            const int wr = cc >> 3, off = (cc & 7) * 4;
            cp_async16(d0 + (uint32_t)(G_WOFF + wr * 36 + off) * 4,
                       Wt + (size_t)(n0 + wr) * 128 + kb * 32 + off);
            if (wcomp)
                cp_async16(d0 + (uint32_t)(G_WLOFF + wr * 36 + off) * 4,
                           wvl + (size_t)(n0 + wr) * 128 + kb * 32 + off);
        }
    };

    float O[8][4];
#pragma unroll
    for (int n = 0; n < 8; n++)
#pragma unroll
        for (int r = 0; r < 4; r++) O[n][r] = 0.f;

    load_tiles(0, 0);
    cp_commit();

    for (int kb = 0; kb < 4; kb++) {
        if (kb < 3) { load_tiles(kb + 1, (kb + 1) & 1); cp_commit(); cp_wait<1>(); }
        else        { cp_wait<0>(); }
        __syncthreads();

        const uint32_t bb = ub + (uint32_t)(kb & 1) * G_BUF * 4;
        const uint32_t aBase = bb + (uint32_t)(m0 + (lane & 15)) * 144 + ((lane >> 4) & 1) * 16;
        const uint32_t bBase = bb + G_WOFF * 4 + (uint32_t)(lane & 7) * 144 + ((lane >> 3) & 3) * 16;

#pragma unroll
        for (int kcp = 0; kcp < 2; kcp++) {
            uint32_t Aa[4], Ab[4];
            ldmatrix_x4(Aa, aBase + (2 * kcp) * 32);
            ldmatrix_x4(Ab, aBase + (2 * kcp + 1) * 32);
#pragma unroll
            for (int nt = 0; nt < 8; nt++) {
                uint32_t Bf[4];
                ldmatrix_x4(Bf, bBase + (uint32_t)nt * 8 * 144 + kcp * 64);
                mma_f16(O[nt], Aa, Bf);
                mma_f16(O[nt], Ab, Bf + 2);
                if (wcomp) {
                    uint32_t Bl[4];
                    ldmatrix_x4(Bl, bBase + (uint32_t)(G_WLOFF - G_WOFF) * 4 +
                                    (uint32_t)nt * 8 * 144 + kcp * 64);
                    mma_f16(O[nt], Aa, Bl);
                    mma_f16(O[nt], Ab, Bl + 2);
                }
            }
        }
        __syncthreads();
    }

    // ---- epilogue: f16 packed out ----
    const int r0 = rowBase + m0 + g;
#pragma unroll
    for (int nt = 0; nt < 8; nt++) {
        const int cg = n0 + nt * 8 + 2 * q4;
        const float b0 = bias[cg], b1 = bias[cg + 1];
        const float c0 = (O[nt][0] + b0) * scale, c1 = (O[nt][1] + b1) * scale;
        const float c2 = (O[nt][2] + b0) * scale, c3 = (O[nt][3] + b1) * scale;
        const int cu = (n0 >> 1) + nt * 4 + q4;
        C16[(size_t)r0 * (N / 2) + cu] = pack_f16x2(c0, c1);
        C16[(size_t)(r0 + 8) * (N / 2) + cu] = pack_f16x2(c2, c3);
    }
}

// ======================================================================
// Output projection GEMM: BM=64, 128 threads, grid (4, 256). f32 out.
// smem u32/buffer: A[64][36] | W[64][36]
// ======================================================================
#define GO_WOFF (64*36)
#define GO_BUF  (2*64*36)               // 4608 u32 per buffer

__global__ void __launch_bounds__(128) gemm_o(
        const uint32_t* __restrict__ A16, const uint32_t* __restrict__ Wt,
        const float* __restrict__ bias, float* __restrict__ Cf) {
    extern __shared__ __align__(16) uint32_t sm[];
    const uint32_t ub = (uint32_t)__cvta_generic_to_shared(sm);

    const int tid = threadIdx.x;
    const int wid = tid >> 5;
    const int lane = tid & 31;
    const int g = lane >> 2, q4 = lane & 3;
    const int rowBase = blockIdx.y * 64;
    const int n0 = blockIdx.x * 64;
    const int m0 = wid * 16;

    auto load_tiles = [&](int kb, int bufsel) {
        const uint32_t d0 = ub + (uint32_t)bufsel * GO_BUF * 4;
        const int ar = tid >> 1, half = (tid & 1) * 16;
        const uint32_t* asrc = A16 + (size_t)(rowBase + ar) * 128 + kb * 32 + half;
        const uint32_t adst = d0 + (uint32_t)(ar * 36 + half) * 4;
#pragma unroll
        for (int u = 0; u < 4; u++) cp_async16(adst + u * 16, asrc + u * 4);
#pragma unroll
        for (int c = 0; c < 4; c++) {
            const int cc = c * 128 + tid;
            const int wr = cc >> 3, off = (cc & 7) * 4;
            cp_async16(d0 + (uint32_t)(GO_WOFF + wr * 36 + off) * 4,
                       Wt + (size_t)(n0 + wr) * 128 + kb * 32 + off);
        }
    };

    float O[8][4];
#pragma unroll
    for (int n = 0; n < 8; n++)
#pragma unroll
        for (int r = 0; r < 4; r++) O[n][r] = 0.f;

    load_tiles(0, 0);
    cp_commit();

    for (int kb = 0; kb < 4; kb++) {
        if (kb < 3) { load_tiles(kb + 1, (kb + 1) & 1); cp_commit(); cp_wait<1>(); }
        else        { cp_wait<0>(); }
        __syncthreads();

        const uint32_t bb = ub + (uint32_t)(kb & 1) * GO_BUF * 4;
        const uint32_t aBase = bb + (uint32_t)(m0 + (lane & 15)) * 144 + ((lane >> 4) & 1) * 16;
        const uint32_t bBase = bb + GO_WOFF * 4 + (uint32_t)(lane & 7) * 144 + ((lane >> 3) & 3) * 16;

#pragma unroll
        for (int kcp = 0; kcp < 2; kcp++) {
            uint32_t Aa[4], Ab[4];
            ldmatrix_x4(Aa, aBase + (2 * kcp) * 32);
            ldmatrix_x4(Ab, aBase + (2 * kcp + 1) * 32);
#pragma unroll
            for (int nt = 0; nt < 8; nt++) {
                uint32_t Bf[4];
                ldmatrix_x4(Bf, bBase + (uint32_t)nt * 8 * 144 + kcp * 64);
                mma_f16(O[nt], Aa, Bf);
                mma_f16(O[nt], Ab, Bf + 2);
            }
        }
        __syncthreads();
    }

    const int r0 = rowBase + m0 + g;
#pragma unroll
    for (int nt = 0; nt < 8; nt++) {
        const int cg = n0 + nt * 8 + 2 * q4;
        const float b0 = bias[cg], b1 = bias[cg + 1];
        *(float2*)&Cf[(size_t)r0 * 256 + cg] = make_float2(O[nt][0] + b0, O[nt][1] + b1);
        *(float2*)&Cf[(size_t)(r0 + 8) * 256 + cg] = make_float2(O[nt][2] + b0, O[nt][3] + b1);
    }
}

// ======================================================================
// fp16 flash attention. Split-S scheduling: each 64-key sub-block handled
// as two independent 32-key halves (S[4][4] live; PV(half0) independent of
// S(half1) -> interleavable MMA streams). Ones-column row sums, log2 exp.
// ======================================================================
#define AT_VOFF (128*36)
#define AT_BUF  (2*128*36)

__global__ void __launch_bounds__(256) attn16(
        const uint32_t* __restrict__ gq, const uint32_t* __restrict__ gk,
        const uint32_t* __restrict__ gv, uint32_t* __restrict__ ao) {
    extern __shared__ __align__(16) uint32_t sm[];
    const uint32_t ub = (uint32_t)__cvta_generic_to_shared(sm);

    const int tid = threadIdx.x;
    const int wid = tid >> 5;
    const int lane = tid & 31;
    const int g = lane >> 2, q4 = lane & 3;

    const int bh = blockIdx.y;
    const int b = bh >> 2, h = bh & 3;
    const int q0 = blockIdx.x * 128;
    const int m0 = q0 + wid * 16;

    // ones-pad init (V u32 cols 32..35, both buffers)
    {
        const int buf = tid >> 7, row = tid & 127;
        uint4 ones = make_uint4(0x3C003C00u, 0x3C003C00u, 0x3C003C00u, 0x3C003C00u);
        *(uint4*)&sm[buf * AT_BUF + AT_VOFF + row * 36 + 32] = ones;
    }

    // Q fragments (resident; scaled by QSCALE in projection)
    uint32_t Qf[4][4];
    {
        const uint32_t* qp = gq + (size_t)(b*TT + m0 + g) * 128 + h * 32;
#pragma unroll
        for (int kc = 0; kc < 4; kc++) {
            const int du = kc * 8 + q4;
            Qf[kc][0] = qp[du];         Qf[kc][1] = qp[8*128 + du];
            Qf[kc][2] = qp[du + 4];     Qf[kc][3] = qp[8*128 + du + 4];
        }
    }

    const int kn = tid >> 1;
    const int half = (tid & 1) * 16;

    auto load_kv = [&](int it, int bufsel) {
        const uint32_t d0 = ub + (uint32_t)bufsel * AT_BUF * 4;
        const int row = b * TT + it * NB + kn;
        const uint32_t* ks = gk + (size_t)row * 128 + h * 32 + half;
        const uint32_t kd = d0 + (uint32_t)(kn * 36 + half) * 4;
#pragma unroll
        for (int u = 0; u < 4; u++) cp_async16(kd + u * 16, ks + u * 4);
        const uint32_t* vs = gv + (size_t)row * 32 + half;
        const uint32_t vd = d0 + (uint32_t)(AT_VOFF + kn * 36 + half) * 4;
#pragma unroll
        for (int u = 0; u < 4; u++) cp_async16(vd + u * 16, vs + u * 4);
    };

    float O[8][4];
#pragma unroll
    for (int n = 0; n < 8; n++)
#pragma unroll
        for (int r = 0; r < 4; r++) O[n][r] = 0.f;
    float Osum[4] = {0.f, 0.f, 0.f, 0.f};

    const int vLaneRow = (lane & 7) + 8 * ((lane >> 3) & 3);

    load_kv(0, 0);
    cp_commit();

    for (int it = 0; it < TT / NB; it++) {
        if (it + 1 < TT / NB) { load_kv(it + 1, (it + 1) & 1); cp_commit(); cp_wait<1>(); }
        else                  { cp_wait<0>(); }
        __syncthreads();

        const uint32_t bb = ub + (uint32_t)(it & 1) * AT_BUF * 4;
        const uint32_t kBase = bb + (uint32_t)(lane & 7) * 144 + ((lane >> 3) & 3) * 16;
        const uint32_t vBase = bb + AT_VOFF * 4 + (uint32_t)vLaneRow * 144;

#pragma unroll
        for (int sub = 0; sub < 2; sub++) {
#pragma unroll
            for (int hf = 0; hf < 2; hf++) {
                float S[4][4];
                // ---- S for 32 keys ----
#pragma unroll
                for (int jj = 0; jj < 4; jj++) {
#pragma unroll
                    for (int r = 0; r < 4; r++) S[jj][r] = 0.f;
                    const uint32_t rowoff = (uint32_t)(sub*64 + (hf*4 + jj)*8) * 144;
#pragma unroll
                    for (int kcp = 0; kcp < 2; kcp++) {
                        uint32_t Bf[4];
                        ldmatrix_x4(Bf, kBase + rowoff + kcp * 64);
                        mma_f16(S[jj], Qf[2*kcp],     Bf);
                        mma_f16(S[jj], Qf[2*kcp + 1], Bf + 2);
                    }
                }
                // ---- p = 2^s ----
#pragma unroll
                for (int jj = 0; jj < 4; jj++) {
                    S[jj][0] = ex2f(S[jj][0]);
                    S[jj][1] = ex2f(S[jj][1]);
                    S[jj][2] = ex2f(S[jj][2]);
                    S[jj][3] = ex2f(S[jj][3]);
                }
                // ---- pack P ----
                uint32_t PhA[4], PhB[4];
                PhA[0] = pack_f16x2(S[0][0], S[0][1]);
                PhA[1] = pack_f16x2(S[0][2], S[0][3]);
                PhA[2] = pack_f16x2(S[1][0], S[1][1]);
                PhA[3] = pack_f16x2(S[1][2], S[1][3]);
                PhB[0] = pack_f16x2(S[2][0], S[2][1]);
                PhB[1] = pack_f16x2(S[2][2], S[2][3]);
                PhB[2] = pack_f16x2(S[3][0], S[3][1]);
                PhB[3] = pack_f16x2(S[3][2], S[3][3]);
                // ---- O += P @ V; 9th n-tile (ones) accumulates row sums ----
                const uint32_t koff = (uint32_t)(sub*64 + hf*32) * 144;
#pragma unroll
                for (int nt = 0; nt < 8; nt++) {
                    uint32_t Vf[4];
                    ldmatrix_x4_t(Vf, vBase + koff + (uint32_t)nt * 16);
                    mma_f16(O[nt], PhA, Vf);
                    mma_f16(O[nt], PhB, Vf + 2);
                }
                {
                    uint32_t Vf[4];
                    ldmatrix_x4_t(Vf, vBase + koff + 8 * 16);
                    mma_f16(Osum, PhA, Vf);
                    mma_f16(Osum, PhB, Vf + 2);
                }
            }
        }
        __syncthreads();
    }

    const float inv0 = 1.f / Osum[0];
    const float inv1 = 1.f / Osum[2];

    uint32_t* dh = ao + (size_t)(b*TT + m0 + g) * 128 + h * 32;
#pragma unroll
    for (int nt = 0; nt < 8; nt++) {
        const int cu = nt * 4 + q4;
        dh[cu]         = pack_f16x2(O[nt][0] * inv0, O[nt][1] * inv0);
        dh[8*128 + cu] = pack_f16x2(O[nt][2] * inv1, O[nt][3] * inv1);
    }
}

// ---------------- launch ----------------
extern "C" void kernel_launch(void* const* d_in, const int* in_sizes, int n_in,
                              void* d_out, int out_size) {
    (void)in_sizes; (void)n_in; (void)out_size;
    const float* query = (const float*)d_in[0];
    const float* key   = (const float*)d_in[1];
    const float* value = (const float*)d_in[2];
    const float* Wq    = (const float*)d_in[3];
    const float* bq    = (const float*)d_in[4];
    const float* Wk    = (const float*)d_in[5];
    const float* bk    = (const float*)d_in[6];
    const float* Wv    = (const float*)d_in[7];
    const float* bv    = (const float*)d_in[8];
    const float* Wo    = (const float*)d_in[9];
    const float* bo    = (const float*)d_in[10];
    float* out = (float*)d_out;

    uint32_t *qi_, *ki_, *vi_, *wq_, *wk_, *wvh_, *wvl_, *wo_;
    uint32_t *q16_, *k16_, *v16_, *ao_;
    cudaGetSymbolAddress((void**)&qi_,  g_qi16);
    cudaGetSymbolAddress((void**)&ki_,  g_ki16);
    cudaGetSymbolAddress((void**)&vi_,  g_vi16);
    cudaGetSymbolAddress((void**)&wq_,  g_wq);
    cudaGetSymbolAddress((void**)&wk_,  g_wk);
    cudaGetSymbolAddress((void**)&wvh_, g_wvh);
    cudaGetSymbolAddress((void**)&wvl_, g_wvl);
    cudaGetSymbolAddress((void**)&wo_,  g_wo);
    cudaGetSymbolAddress((void**)&q16_, g_q16);
    cudaGetSymbolAddress((void**)&k16_, g_k16);
    cudaGetSymbolAddress((void**)&v16_, g_v16);
    cudaGetSymbolAddress((void**)&ao_,  g_ao16);

    const int sm_qkv = 2 * G_BUF * 4;    // 55296
    const int sm_o   = 2 * GO_BUF * 4;   // 36864
    const int sm_at  = 2 * AT_BUF * 4;   // 73728
    cudaFuncSetAttribute(gemm_qkv, cudaFuncAttributeMaxDynamicSharedMemorySize, sm_qkv);
    cudaFuncSetAttribute(gemm_o,   cudaFuncAttributeMaxDynamicSharedMemorySize, sm_o);
    cudaFuncSetAttribute(attn16,   cudaFuncAttributeMaxDynamicSharedMemorySize, sm_at);

    // 1) prepass (inputs + all weights, one launch)
    prep<<<1440, 256>>>(query, key, value, Wq, Wk, Wv, Wo,
                        qi_, ki_, vi_, wq_, wk_, wvh_, wvl_, wo_);
    // 2) fused Q/K/V projections (BM=64, 128 threads)
    gemm_qkv<<<dim3(4, 256, 3), 128, sm_qkv>>>(qi_, ki_, vi_, wq_, wk_, wvh_, wvl_,
                                               bq, bk, bv, q16_, k16_, v16_);
    // 3) attention
    attn16<<<dim3(TT / 128, BATCH * NHEAD), 256, sm_at>>>(q16_, k16_, v16_, ao_);
    // 4) output projection (BM=64, 128 threads)
    gemm_o<<<dim3(4, 256), 128, sm_o>>>(ao_, wo_, bo, out);
}

// round 12
// speedup vs baseline: 1.0580x; 1.0446x over previous
#include <cuda_runtime.h>
#include <cuda_fp16.h>
#include <math.h>
#include <stdint.h>

// Problem constants
#define BATCH 16
#define TT    1024
#define DMODEL 256
#define NHEAD 4
#define DKEY  64
#define HDIM  256
#define MROWS (BATCH*TT)   // 16384
#define NB    128          // keys per block

// Q pre-scale: (1/sqrt(64)) * log2(e)  -> scores come out in log2 domain
#define QSCALE 0.1803368801111204f

// ---------------- device scratch ----------------
__device__ uint32_t g_qi16[MROWS * DMODEL / 2];
__device__ uint32_t g_ki16[MROWS * DMODEL / 2];
__device__ uint32_t g_vi16[MROWS * DMODEL / 2];
__device__ uint32_t g_wq [HDIM * DMODEL / 2];
__device__ uint32_t g_wk [HDIM * DMODEL / 2];
__device__ uint32_t g_wvh[DKEY * DMODEL / 2];
__device__ uint32_t g_wvl[DKEY * DMODEL / 2];
__device__ uint32_t g_wo [HDIM * DMODEL / 2];
__device__ uint32_t g_q16[MROWS * HDIM / 2];
__device__ uint32_t g_k16[MROWS * HDIM / 2];
__device__ uint32_t g_v16[MROWS * DKEY / 2];
__device__ uint32_t g_ao16[MROWS * HDIM / 2];

// =============== helpers ===============
__device__ __forceinline__ uint32_t pack_f16x2(float lo, float hi) {
    uint32_t w;
    asm("cvt.rn.f16x2.f32 %0, %1, %2;" : "=r"(w) : "f"(hi), "f"(lo));
    return w;
}
__device__ __forceinline__ float f16_lo_f32(uint32_t w) {
    float f;
    asm("{.reg .b16 l,h; mov.b32 {l,h}, %1; cvt.f32.f16 %0, l;}" : "=f"(f) : "r"(w));
    return f;
}
__device__ __forceinline__ float f16_hi_f32(uint32_t w) {
    float f;
    asm("{.reg .b16 l,h; mov.b32 {l,h}, %1; cvt.f32.f16 %0, h;}" : "=f"(f) : "r"(w));
    return f;
}
__device__ __forceinline__ float ex2f(float x) {
    float y;
    asm("ex2.approx.ftz.f32 %0, %1;" : "=f"(y) : "f"(x));
    return y;
}
__device__ __forceinline__ void mma_f16(float* c, const uint32_t* a, const uint32_t* b) {
    asm volatile(
        "mma.sync.aligned.m16n8k16.row.col.f32.f16.f16.f32 "
        "{%0,%1,%2,%3}, {%4,%5,%6,%7}, {%8,%9}, {%0,%1,%2,%3};"
        : "+f"(c[0]), "+f"(c[1]), "+f"(c[2]), "+f"(c[3])
        : "r"(a[0]), "r"(a[1]), "r"(a[2]), "r"(a[3]), "r"(b[0]), "r"(b[1]));
}
__device__ __forceinline__ void ldmatrix_x4(uint32_t* r, uint32_t addr) {
    asm volatile("ldmatrix.sync.aligned.m8n8.x4.shared.b16 {%0,%1,%2,%3}, [%4];"
        : "=r"(r[0]), "=r"(r[1]), "=r"(r[2]), "=r"(r[3]) : "r"(addr));
}
__device__ __forceinline__ void ldmatrix_x4_t(uint32_t* r, uint32_t addr) {
    asm volatile("ldmatrix.sync.aligned.m8n8.x4.trans.shared.b16 {%0,%1,%2,%3}, [%4];"
        : "=r"(r[0]), "=r"(r[1]), "=r"(r[2]), "=r"(r[3]) : "r"(addr));
}
__device__ __forceinline__ void cp_async16(uint32_t dst, const void* src) {
    asm volatile("cp.async.cg.shared.global [%0], [%1], 16;" :: "r"(dst), "l"(src) : "memory");
}
__device__ __forceinline__ void cp_commit() { asm volatile("cp.async.commit_group;" ::: "memory"); }
template<int W> __device__ __forceinline__ void cp_wait() {
    asm volatile("cp.async.wait_group %0;" :: "n"(W) : "memory");
}

// ======================================================================
// prep: ONE launch. Blocks [0,1024): input f32->f16. Blocks [1024,1440):
// weight transpose/convert (Wq 128 | Wk 128 | Wv 32 (+lo) | Wo 128 blocks).
// ======================================================================
__global__ void prep(const float* __restrict__ q, const float* __restrict__ k,
                     const float* __restrict__ v,
                     const float* __restrict__ Wq, const float* __restrict__ Wk,
                     const float* __restrict__ Wv, const float* __restrict__ Wo,
                     uint32_t* __restrict__ q16, uint32_t* __restrict__ k16,
                     uint32_t* __restrict__ v16,
                     uint32_t* __restrict__ wq, uint32_t* __restrict__ wk,
                     uint32_t* __restrict__ wvh, uint32_t* __restrict__ wvl,
                     uint32_t* __restrict__ wo) {
    const int bx = blockIdx.x;
    if (bx < 1024) {
        const int n = MROWS * DMODEL / 4;
        for (int i = bx * 256 + threadIdx.x; i < n; i += 1024 * 256) {
            float4 a = ((const float4*)q)[i];
            ((uint2*)q16)[i] = make_uint2(pack_f16x2(a.x, a.y), pack_f16x2(a.z, a.w));
            a = ((const float4*)k)[i];
            ((uint2*)k16)[i] = make_uint2(pack_f16x2(a.x, a.y), pack_f16x2(a.z, a.w));
            a = ((const float4*)v)[i];
            ((uint2*)v16)[i] = make_uint2(pack_f16x2(a.x, a.y), pack_f16x2(a.z, a.w));
        }
        return;
    }
    const int wb = bx - 1024;   // 0..415
    int which, setbase;
    if      (wb < 128) { which = 0; setbase = 0;   }
    else if (wb < 256) { which = 1; setbase = 128; }
    else if (wb < 288) { which = 2; setbase = 256; }
    else               { which = 3; setbase = 288; }
    const int N = (which == 2) ? 64 : 256;
    const int t = (wb - setbase) * 256 + threadIdx.x;
    if (t >= N * 128) return;
    const float* W = (which == 0) ? Wq : (which == 1) ? Wk : (which == 2) ? Wv : Wo;
    uint32_t* Wt   = (which == 0) ? wq : (which == 1) ? wk : (which == 2) ? wvh : wo;
    const int n = t % N;
    const int kp = t / N;
    const float w0 = W[(size_t)(2 * kp) * N + n];
    const float w1 = W[(size_t)(2 * kp + 1) * N + n];
    const uint32_t hw = pack_f16x2(w0, w1);
    Wt[(size_t)n * 128 + kp] = hw;
    if (which == 2)
        wvl[(size_t)n * 128 + kp] = pack_f16x2(w0 - f16_lo_f32(hw), w1 - f16_hi_f32(hw));
}

// ======================================================================
// Barrier-free GEMM core: BM=64, BN=64, full K=256 resident in smem.
// 128 threads (4 warps, m16 x n64 each). ONE cp.async wait + ONE barrier,
// then all 8 k-chunks of ldmatrix+MMA as a straight stream.
// smem u32: A[64][132] | W[64][132]  (row stride 528B -> bank = 4r mod 32)
// ======================================================================
#define GR    132
#define G_A   0
#define G_W   (64*GR)
#define G_SM  (2*64*GR)                 // 16896 u32 = 67584 B

// load a full 64x256-f16 tile (as [row][128] u32) into smem region (u32 idx)
__device__ __forceinline__ void g64_load_tile(uint32_t ub, int region,
                                              const uint32_t* __restrict__ src,
                                              int row0, int tid) {
#pragma unroll
    for (int i = 0; i < 16; i++) {
        const int c = i * 128 + tid;          // 2048 16B-chunks
        const int row = c >> 5, off = (c & 31) * 4;
        cp_async16(ub + (uint32_t)(region + row * GR + off) * 4,
                   src + (size_t)(row0 + row) * 128 + off);
    }
}

__device__ __forceinline__ void g64_compute(uint32_t ub, float O[8][4],
                                            int m0, int lane) {
    const uint32_t aBase = ub + (uint32_t)(m0 + (lane & 15)) * (GR*4) + ((lane >> 4) & 1) * 16;
    const uint32_t bBase = ub + (uint32_t)G_W * 4 + (uint32_t)(lane & 7) * (GR*4) + ((lane >> 3) & 3) * 16;
#pragma unroll
    for (int kb = 0; kb < 4; kb++) {
#pragma unroll
        for (int kcp = 0; kcp < 2; kcp++) {
            uint32_t Aa[4], Ab[4];
            ldmatrix_x4(Aa, aBase + kb * 128 + (2 * kcp) * 32);
            ldmatrix_x4(Ab, aBase + kb * 128 + (2 * kcp + 1) * 32);
#pragma unroll
            for (int nt = 0; nt < 8; nt++) {
                uint32_t Bf[4];
                ldmatrix_x4(Bf, bBase + (uint32_t)nt * 8 * (GR*4) + kb * 128 + kcp * 64);
                mma_f16(O[nt], Aa, Bf);
                mma_f16(O[nt], Ab, Bf + 2);
            }
        }
    }
}

// ======================================================================
// Fused QKV projection, grid (4, 256, 3), 128 threads.
// z=0: Q (scale=QSCALE); z=1: K; z=2: V (N=64, x==0 only; W-comp via
// second pass that reloads Wlo into the W smem region).
// ======================================================================
__global__ void __launch_bounds__(128) gemm_qkv(
        const uint32_t* __restrict__ qi, const uint32_t* __restrict__ ki,
        const uint32_t* __restrict__ vi,
        const uint32_t* __restrict__ wq, const uint32_t* __restrict__ wk,
        const uint32_t* __restrict__ wvh, const uint32_t* __restrict__ wvl,
        const float* __restrict__ bq, const float* __restrict__ bk,
        const float* __restrict__ bv,
        uint32_t* __restrict__ q16, uint32_t* __restrict__ k16,
        uint32_t* __restrict__ v16) {
    const int z = blockIdx.z;
    const bool wcomp = (z == 2);
    if (wcomp && blockIdx.x != 0) return;

    const uint32_t* A16 = (z == 0) ? qi : (z == 1) ? ki : vi;
    const uint32_t* Wt  = (z == 0) ? wq : (z == 1) ? wk : wvh;
    const float* bias   = (z == 0) ? bq : (z == 1) ? bk : bv;
    uint32_t* C16       = (z == 0) ? q16 : (z == 1) ? k16 : v16;
    const int N         = wcomp ? 64 : 256;
    const float scale   = (z == 0) ? QSCALE : 1.0f;

    extern __shared__ __align__(16) uint32_t sm[];
    const uint32_t ub = (uint32_t)__cvta_generic_to_shared(sm);

    const int tid = threadIdx.x;
    const int wid = tid >> 5;
    const int lane = tid & 31;
    const int g = lane >> 2, q4 = lane & 3;
    const int rowBase = blockIdx.y * 64;
    const int n0 = blockIdx.x * 64;
    const int m0 = wid * 16;

    g64_load_tile(ub, G_A, A16, rowBase, tid);
    g64_load_tile(ub, G_W, Wt, n0, tid);
    cp_commit();
    cp_wait<0>();
    __syncthreads();

    float O[8][4];
#pragma unroll
    for (int n = 0; n < 8; n++)
#pragma unroll
        for (int r = 0; r < 4; r++) O[n][r] = 0.f;

    g64_compute(ub, O, m0, lane);

    if (wcomp) {
        // second pass: Wlo into the W region, accumulate (A still resident)
        __syncthreads();
        g64_load_tile(ub, G_W, wvl, n0, tid);
        cp_commit();
        cp_wait<0>();
        __syncthreads();
        g64_compute(ub, O, m0, lane);
    }

    // ---- epilogue: f16 packed out ----
    const int r0 = rowBase + m0 + g;
#pragma unroll
    for (int nt = 0; nt < 8; nt++) {
        const int cg = n0 + nt * 8 + 2 * q4;
        const float b0 = bias[cg], b1 = bias[cg + 1];
        const float c0 = (O[nt][0] + b0) * scale, c1 = (O[nt][1] + b1) * scale;
        const float c2 = (O[nt][2] + b0) * scale, c3 = (O[nt][3] + b1) * scale;
        const int cu = (n0 >> 1) + nt * 4 + q4;
        C16[(size_t)r0 * (N / 2) + cu] = pack_f16x2(c0, c1);
        C16[(size_t)(r0 + 8) * (N / 2) + cu] = pack_f16x2(c2, c3);
    }
}

// ======================================================================
// Output projection: grid (4, 256), 128 threads, f32 out.
// ======================================================================
__global__ void __launch_bounds__(128) gemm_o(
        const uint32_t* __restrict__ A16, const uint32_t* __restrict__ Wt,
        const float* __restrict__ bias, float* __restrict__ Cf) {
    extern __shared__ __align__(16) uint32_t sm[];
    const uint32_t ub = (uint32_t)__cvta_generic_to_shared(sm);

    const int tid = threadIdx.x;
    const int wid = tid >> 5;
    const int lane = tid & 31;
    const int g = lane >> 2, q4 = lane & 3;
    const int rowBase = blockIdx.y * 64;
    const int n0 = blockIdx.x * 64;
    const int m0 = wid * 16;

    g64_load_tile(ub, G_A, A16, rowBase, tid);
    g64_load_tile(ub, G_W, Wt, n0, tid);
    cp_commit();
    cp_wait<0>();
    __syncthreads();

    float O[8][4];
#pragma unroll
    for (int n = 0; n < 8; n++)
#pragma unroll
        for (int r = 0; r < 4; r++) O[n][r] = 0.f;

    g64_compute(ub, O, m0, lane);

    const int r0 = rowBase + m0 + g;
#pragma unroll
    for (int nt = 0; nt < 8; nt++) {
        const int cg = n0 + nt * 8 + 2 * q4;
        const float b0 = bias[cg], b1 = bias[cg + 1];
        *(float2*)&Cf[(size_t)r0 * 256 + cg] = make_float2(O[nt][0] + b0, O[nt][1] + b1);
        *(float2*)&Cf[(size_t)(r0 + 8) * 256 + cg] = make_float2(O[nt][2] + b0, O[nt][3] + b1);
    }
}

// ======================================================================
// fp16 flash attention (unchanged, proven at 152 us total).
// ======================================================================
#define AT_VOFF (128*36)
#define AT_BUF  (2*128*36)

__global__ void __launch_bounds__(256) attn16(
        const uint32_t* __restrict__ gq, const uint32_t* __restrict__ gk,
        const uint32_t* __restrict__ gv, uint32_t* __restrict__ ao) {
    extern __shared__ __align__(16) uint32_t sm[];
    const uint32_t ub = (uint32_t)__cvta_generic_to_shared(sm);

    const int tid = threadIdx.x;
    const int wid = tid >> 5;
    const int lane = tid & 31;
    const int g = lane >> 2, q4 = lane & 3;

    const int bh = blockIdx.y;
    const int b = bh >> 2, h = bh & 3;
    const int q0 = blockIdx.x * 128;
    const int m0 = q0 + wid * 16;

    // ones-pad init (V u32 cols 32..35, both buffers)
    {
        const int buf = tid >> 7, row = tid & 127;
        uint4 ones = make_uint4(0x3C003C00u, 0x3C003C00u, 0x3C003C00u, 0x3C003C00u);
        *(uint4*)&sm[buf * AT_BUF + AT_VOFF + row * 36 + 32] = ones;
    }

    // Q fragments (resident; scaled by QSCALE in projection)
    uint32_t Qf[4][4];
    {
        const uint32_t* qp = gq + (size_t)(b*TT + m0 + g) * 128 + h * 32;
#pragma unroll
        for (int kc = 0; kc < 4; kc++) {
            const int du = kc * 8 + q4;
            Qf[kc][0] = qp[du];         Qf[kc][1] = qp[8*128 + du];
            Qf[kc][2] = qp[du + 4];     Qf[kc][3] = qp[8*128 + du + 4];
        }
    }

    const int kn = tid >> 1;
    const int half = (tid & 1) * 16;

    auto load_kv = [&](int it, int bufsel) {
        const uint32_t d0 = ub + (uint32_t)bufsel * AT_BUF * 4;
        const int row = b * TT + it * NB + kn;
        const uint32_t* ks = gk + (size_t)row * 128 + h * 32 + half;
        const uint32_t kd = d0 + (uint32_t)(kn * 36 + half) * 4;
#pragma unroll
        for (int u = 0; u < 4; u++) cp_async16(kd + u * 16, ks + u * 4);
        const uint32_t* vs = gv + (size_t)row * 32 + half;
        const uint32_t vd = d0 + (uint32_t)(AT_VOFF + kn * 36 + half) * 4;
#pragma unroll
        for (int u = 0; u < 4; u++) cp_async16(vd + u * 16, vs + u * 4);
    };

    float O[8][4];
#pragma unroll
    for (int n = 0; n < 8; n++)
#pragma unroll
        for (int r = 0; r < 4; r++) O[n][r] = 0.f;
    float Osum[4] = {0.f, 0.f, 0.f, 0.f};

    const int vLaneRow = (lane & 7) + 8 * ((lane >> 3) & 3);

    load_kv(0, 0);
    cp_commit();

    for (int it = 0; it < TT / NB; it++) {
        if (it + 1 < TT / NB) { load_kv(it + 1, (it + 1) & 1); cp_commit(); cp_wait<1>(); }
        else                  { cp_wait<0>(); }
        __syncthreads();

        const uint32_t bb = ub + (uint32_t)(it & 1) * AT_BUF * 4;
        const uint32_t kBase = bb + (uint32_t)(lane & 7) * 144 + ((lane >> 3) & 3) * 16;
        const uint32_t vBase = bb + AT_VOFF * 4 + (uint32_t)vLaneRow * 144;

#pragma unroll
        for (int sub = 0; sub < 2; sub++) {
#pragma unroll
            for (int hf = 0; hf < 2; hf++) {
                float S[4][4];
#pragma unroll
                for (int jj = 0; jj < 4; jj++) {
#pragma unroll
                    for (int r = 0; r < 4; r++) S[jj][r] = 0.f;
                    const uint32_t rowoff = (uint32_t)(sub*64 + (hf*4 + jj)*8) * 144;
#pragma unroll
                    for (int kcp = 0; kcp < 2; kcp++) {
                        uint32_t Bf[4];
                        ldmatrix_x4(Bf, kBase + rowoff + kcp * 64);
                        mma_f16(S[jj], Qf[2*kcp],     Bf);
                        mma_f16(S[jj], Qf[2*kcp + 1], Bf + 2);
                    }
                }
#pragma unroll
                for (int jj = 0; jj < 4; jj++) {
                    S[jj][0] = ex2f(S[jj][0]);
                    S[jj][1] = ex2f(S[jj][1]);
                    S[jj][2] = ex2f(S[jj][2]);
                    S[jj][3] = ex2f(S[jj][3]);
                }
                uint32_t PhA[4], PhB[4];
                PhA[0] = pack_f16x2(S[0][0], S[0][1]);
                PhA[1] = pack_f16x2(S[0][2], S[0][3]);
                PhA[2] = pack_f16x2(S[1][0], S[1][1]);
                PhA[3] = pack_f16x2(S[1][2], S[1][3]);
                PhB[0] = pack_f16x2(S[2][0], S[2][1]);
                PhB[1] = pack_f16x2(S[2][2], S[2][3]);
                PhB[2] = pack_f16x2(S[3][0], S[3][1]);
                PhB[3] = pack_f16x2(S[3][2], S[3][3]);
                const uint32_t koff = (uint32_t)(sub*64 + hf*32) * 144;
#pragma unroll
                for (int nt = 0; nt < 8; nt++) {
                    uint32_t Vf[4];
                    ldmatrix_x4_t(Vf, vBase + koff + (uint32_t)nt * 16);
                    mma_f16(O[nt], PhA, Vf);
                    mma_f16(O[nt], PhB, Vf + 2);
                }
                {
                    uint32_t Vf[4];
                    ldmatrix_x4_t(Vf, vBase + koff + 8 * 16);
                    mma_f16(Osum, PhA, Vf);
                    mma_f16(Osum, PhB, Vf + 2);
                }
            }
        }
        __syncthreads();
    }

    const float inv0 = 1.f / Osum[0];
    const float inv1 = 1.f / Osum[2];

    uint32_t* dh = ao + (size_t)(b*TT + m0 + g) * 128 + h * 32;
#pragma unroll
    for (int nt = 0; nt < 8; nt++) {
        const int cu = nt * 4 + q4;
        dh[cu]         = pack_f16x2(O[nt][0] * inv0, O[nt][1] * inv0);
        dh[8*128 + cu] = pack_f16x2(O[nt][2] * inv1, O[nt][3] * inv1);
    }
}

// ---------------- launch ----------------
extern "C" void kernel_launch(void* const* d_in, const int* in_sizes, int n_in,
                              void* d_out, int out_size) {
    (void)in_sizes; (void)n_in; (void)out_size;
    const float* query = (const float*)d_in[0];
    const float* key   = (const float*)d_in[1];
    const float* value = (const float*)d_in[2];
    const float* Wq    = (const float*)d_in[3];
    const float* bq    = (const float*)d_in[4];
    const float* Wk    = (const float*)d_in[5];
    const float* bk    = (const float*)d_in[6];
    const float* Wv    = (const float*)d_in[7];
    const float* bv    = (const float*)d_in[8];
    const float* Wo    = (const float*)d_in[9];
    const float* bo    = (const float*)d_in[10];
    float* out = (float*)d_out;

    uint32_t *qi_, *ki_, *vi_, *wq_, *wk_, *wvh_, *wvl_, *wo_;
    uint32_t *q16_, *k16_, *v16_, *ao_;
    cudaGetSymbolAddress((void**)&qi_,  g_qi16);
    cudaGetSymbolAddress((void**)&ki_,  g_ki16);
    cudaGetSymbolAddress((void**)&vi_,  g_vi16);
    cudaGetSymbolAddress((void**)&wq_,  g_wq);
    cudaGetSymbolAddress((void**)&wk_,  g_wk);
    cudaGetSymbolAddress((void**)&wvh_, g_wvh);
    cudaGetSymbolAddress((void**)&wvl_, g_wvl);
    cudaGetSymbolAddress((void**)&wo_,  g_wo);
    cudaGetSymbolAddress((void**)&q16_, g_q16);
    cudaGetSymbolAddress((void**)&k16_, g_k16);
    cudaGetSymbolAddress((void**)&v16_, g_v16);
    cudaGetSymbolAddress((void**)&ao_,  g_ao16);

    const int sm_g  = G_SM * 4;          // 67584
    const int sm_at = 2 * AT_BUF * 4;    // 73728
    cudaFuncSetAttribute(gemm_qkv, cudaFuncAttributeMaxDynamicSharedMemorySize, sm_g);
    cudaFuncSetAttribute(gemm_o,   cudaFuncAttributeMaxDynamicSharedMemorySize, sm_g);
    cudaFuncSetAttribute(attn16,   cudaFuncAttributeMaxDynamicSharedMemorySize, sm_at);

    // 1) prepass (inputs + all weights, one launch)
    prep<<<1440, 256>>>(query, key, value, Wq, Wk, Wv, Wo,
                        qi_, ki_, vi_, wq_, wk_, wvh_, wvl_, wo_);
    // 2) fused Q/K/V projections (barrier-free mainloop)
    gemm_qkv<<<dim3(4, 256, 3), 128, sm_g>>>(qi_, ki_, vi_, wq_, wk_, wvh_, wvl_,
                                             bq, bk, bv, q16_, k16_, v16_);
    // 3) attention
    attn16<<<dim3(TT / 128, BATCH * NHEAD), 256, sm_at>>>(q16_, k16_, v16_, ao_);
    // 4) output projection (barrier-free mainloop)
    gemm_o<<<dim3(4, 256), 128, sm_g>>>(ao_, wo_, bo, out);
}

// round 13
// speedup vs baseline: 1.0833x; 1.0239x over previous
#include <cuda_runtime.h>
#include <cuda_fp16.h>
#include <math.h>
#include <stdint.h>

// Problem constants
#define BATCH 16
#define TT    1024
#define DMODEL 256
#define NHEAD 4
#define DKEY  64
#define HDIM  256
#define MROWS (BATCH*TT)   // 16384
#define NB    128          // keys per block

// Q pre-scale: (1/sqrt(64)) * log2(e)  -> scores come out in log2 domain
#define QSCALE 0.1803368801111204f

// ---------------- device scratch ----------------
__device__ uint32_t g_qi16[MROWS * DMODEL / 2];
__device__ uint32_t g_ki16[MROWS * DMODEL / 2];
__device__ uint32_t g_vi16[MROWS * DMODEL / 2];
__device__ uint32_t g_wq [HDIM * DMODEL / 2];
__device__ uint32_t g_wk [HDIM * DMODEL / 2];
__device__ uint32_t g_wvh[DKEY * DMODEL / 2];
__device__ uint32_t g_wvl[DKEY * DMODEL / 2];
__device__ uint32_t g_wo [HDIM * DMODEL / 2];
__device__ uint32_t g_q16[MROWS * HDIM / 2];
__device__ uint32_t g_k16[MROWS * HDIM / 2];
__device__ uint32_t g_v16[MROWS * DKEY / 2];
__device__ uint32_t g_ao16[MROWS * HDIM / 2];

// =============== helpers ===============
__device__ __forceinline__ uint32_t pack_f16x2(float lo, float hi) {
    uint32_t w;
    asm("cvt.rn.f16x2.f32 %0, %1, %2;" : "=r"(w) : "f"(hi), "f"(lo));
    return w;
}
__device__ __forceinline__ float f16_lo_f32(uint32_t w) {
    float f;
    asm("{.reg .b16 l,h; mov.b32 {l,h}, %1; cvt.f32.f16 %0, l;}" : "=f"(f) : "r"(w));
    return f;
}
__device__ __forceinline__ float f16_hi_f32(uint32_t w) {
    float f;
    asm("{.reg .b16 l,h; mov.b32 {l,h}, %1; cvt.f32.f16 %0, h;}" : "=f"(f) : "r"(w));
    return f;
}
__device__ __forceinline__ float ex2f(float x) {
    float y;
    asm("ex2.approx.ftz.f32 %0, %1;" : "=f"(y) : "f"(x));
    return y;
}
__device__ __forceinline__ void mma_f16(float* c, const uint32_t* a, const uint32_t* b) {
    asm volatile(
        "mma.sync.aligned.m16n8k16.row.col.f32.f16.f16.f32 "
        "{%0,%1,%2,%3}, {%4,%5,%6,%7}, {%8,%9}, {%0,%1,%2,%3};"
        : "+f"(c[0]), "+f"(c[1]), "+f"(c[2]), "+f"(c[3])
        : "r"(a[0]), "r"(a[1]), "r"(a[2]), "r"(a[3]), "r"(b[0]), "r"(b[1]));
}
__device__ __forceinline__ void ldmatrix_x4(uint32_t* r, uint32_t addr) {
    asm volatile("ldmatrix.sync.aligned.m8n8.x4.shared.b16 {%0,%1,%2,%3}, [%4];"
        : "=r"(r[0]), "=r"(r[1]), "=r"(r[2]), "=r"(r[3]) : "r"(addr));
}
__device__ __forceinline__ void ldmatrix_x4_t(uint32_t* r, uint32_t addr) {
    asm volatile("ldmatrix.sync.aligned.m8n8.x4.trans.shared.b16 {%0,%1,%2,%3}, [%4];"
        : "=r"(r[0]), "=r"(r[1]), "=r"(r[2]), "=r"(r[3]) : "r"(addr));
}
__device__ __forceinline__ void cp_async16(uint32_t dst, const void* src) {
    asm volatile("cp.async.cg.shared.global [%0], [%1], 16;" :: "r"(dst), "l"(src) : "memory");
}
__device__ __forceinline__ void cp_commit() { asm volatile("cp.async.commit_group;" ::: "memory"); }
template<int W> __device__ __forceinline__ void cp_wait() {
    asm volatile("cp.async.wait_group %0;" :: "n"(W) : "memory");
}

// ======================================================================
// prep: ONE launch. Blocks [0,1024): input f32->f16. Blocks [1024,1440):
// weight transpose/convert (Wq 128 | Wk 128 | Wv 32 (+lo) | Wo 128 blocks).
// ======================================================================
__global__ void prep(const float* __restrict__ q, const float* __restrict__ k,
                     const float* __restrict__ v,
                     const float* __restrict__ Wq, const float* __restrict__ Wk,
                     const float* __restrict__ Wv, const float* __restrict__ Wo,
                     uint32_t* __restrict__ q16, uint32_t* __restrict__ k16,
                     uint32_t* __restrict__ v16,
                     uint32_t* __restrict__ wq, uint32_t* __restrict__ wk,
                     uint32_t* __restrict__ wvh, uint32_t* __restrict__ wvl,
                     uint32_t* __restrict__ wo) {
    const int bx = blockIdx.x;
    if (bx < 1024) {
        const int n = MROWS * DMODEL / 4;
        for (int i = bx * 256 + threadIdx.x; i < n; i += 1024 * 256) {
            float4 a = ((const float4*)q)[i];
            ((uint2*)q16)[i] = make_uint2(pack_f16x2(a.x, a.y), pack_f16x2(a.z, a.w));
            a = ((const float4*)k)[i];
            ((uint2*)k16)[i] = make_uint2(pack_f16x2(a.x, a.y), pack_f16x2(a.z, a.w));
            a = ((const float4*)v)[i];
            ((uint2*)v16)[i] = make_uint2(pack_f16x2(a.x, a.y), pack_f16x2(a.z, a.w));
        }
        return;
    }
    const int wb = bx - 1024;   // 0..415
    int which, setbase;
    if      (wb < 128) { which = 0; setbase = 0;   }
    else if (wb < 256) { which = 1; setbase = 128; }
    else if (wb < 288) { which = 2; setbase = 256; }
    else               { which = 3; setbase = 288; }
    const int N = (which == 2) ? 64 : 256;
    const int t = (wb - setbase) * 256 + threadIdx.x;
    if (t >= N * 128) return;
    const float* W = (which == 0) ? Wq : (which == 1) ? Wk : (which == 2) ? Wv : Wo;
    uint32_t* Wt   = (which == 0) ? wq : (which == 1) ? wk : (which == 2) ? wvh : wo;
    const int n = t % N;
    const int kp = t / N;
    const float w0 = W[(size_t)(2 * kp) * N + n];
    const float w1 = W[(size_t)(2 * kp + 1) * N + n];
    const uint32_t hw = pack_f16x2(w0, w1);
    Wt[(size_t)n * 128 + kp] = hw;
    if (which == 2)
        wvl[(size_t)n * 128 + kp] = pack_f16x2(w0 - f16_lo_f32(hw), w1 - f16_hi_f32(hw));
}

// ======================================================================
// Barrier-free GEMM core: BM=64, BN=64, full K=256 resident in smem.
// 256 threads = 8 warps in a 4x2 grid: warp = m16 x n32 (O[4][4]).
// ONE cp.async wait + ONE barrier, then straight ldmatrix+MMA stream.
// smem u32: A[64][132] | W[64][132]  (row stride 528B -> bank = 4r mod 32)
// ======================================================================
#define GR    132
#define G_A   0
#define G_W   (64*GR)
#define G_SM  (2*64*GR)                 // 16896 u32 = 67584 B

// load a full 64x256-f16 tile (as [row][128] u32) into smem region (256 thr)
__device__ __forceinline__ void g64_load_tile(uint32_t ub, int region,
                                              const uint32_t* __restrict__ src,
                                              int row0, int tid) {
#pragma unroll
    for (int i = 0; i < 8; i++) {
        const int c = i * 256 + tid;          // 2048 16B-chunks
        const int row = c >> 5, off = (c & 31) * 4;
        cp_async16(ub + (uint32_t)(region + row * GR + off) * 4,
                   src + (size_t)(row0 + row) * 128 + off);
    }
}

// warp computes m16 (at m0) x n32 (at nwoff within the 64-col tile)
__device__ __forceinline__ void g64_compute(uint32_t ub, float O[4][4],
                                            int m0, int nwoff, int lane) {
    const uint32_t aBase = ub + (uint32_t)(m0 + (lane & 15)) * (GR*4) + ((lane >> 4) & 1) * 16;
    const uint32_t bBase = ub + (uint32_t)G_W * 4 +
                           (uint32_t)(nwoff + (lane & 7)) * (GR*4) + ((lane >> 3) & 3) * 16;
#pragma unroll
    for (int kb = 0; kb < 4; kb++) {
#pragma unroll
        for (int kcp = 0; kcp < 2; kcp++) {
            uint32_t Aa[4], Ab[4];
            ldmatrix_x4(Aa, aBase + kb * 128 + (2 * kcp) * 32);
            ldmatrix_x4(Ab, aBase + kb * 128 + (2 * kcp + 1) * 32);
#pragma unroll
            for (int nt = 0; nt < 4; nt++) {
                uint32_t Bf[4];
                ldmatrix_x4(Bf, bBase + (uint32_t)nt * 8 * (GR*4) + kb * 128 + kcp * 64);
                mma_f16(O[nt], Aa, Bf);
                mma_f16(O[nt], Ab, Bf + 2);
            }
        }
    }
}

// ======================================================================
// Fused QKV projection, grid (4, 256, 3), 256 threads.
// z=0: Q (scale=QSCALE); z=1: K; z=2: V (N=64, x==0 only; W-comp via
// second pass that reloads Wlo into the W smem region).
// ======================================================================
__global__ void __launch_bounds__(256) gemm_qkv(
        const uint32_t* __restrict__ qi, const uint32_t* __restrict__ ki,
        const uint32_t* __restrict__ vi,
        const uint32_t* __restrict__ wq, const uint32_t* __restrict__ wk,
        const uint32_t* __restrict__ wvh, const uint32_t* __restrict__ wvl,
        const float* __restrict__ bq, const float* __restrict__ bk,
        const float* __restrict__ bv,
        uint32_t* __restrict__ q16, uint32_t* __restrict__ k16,
        uint32_t* __restrict__ v16) {
    const int z = blockIdx.z;
    const bool wcomp = (z == 2);
    if (wcomp && blockIdx.x != 0) return;

    const uint32_t* A16 = (z == 0) ? qi : (z == 1) ? ki : vi;
    const uint32_t* Wt  = (z == 0) ? wq : (z == 1) ? wk : wvh;
    const float* bias   = (z == 0) ? bq : (z == 1) ? bk : bv;
    uint32_t* C16       = (z == 0) ? q16 : (z == 1) ? k16 : v16;
    const int N         = wcomp ? 64 : 256;
    const float scale   = (z == 0) ? QSCALE : 1.0f;

    extern __shared__ __align__(16) uint32_t sm[];
    const uint32_t ub = (uint32_t)__cvta_generic_to_shared(sm);

    const int tid = threadIdx.x;
    const int wid = tid >> 5;
    const int lane = tid & 31;
    const int g = lane >> 2, q4 = lane & 3;
    const int rowBase = blockIdx.y * 64;
    const int n0 = blockIdx.x * 64;
    const int m0 = (wid & 3) * 16;
    const int nwoff = (wid >> 2) * 32;

    g64_load_tile(ub, G_A, A16, rowBase, tid);
    g64_load_tile(ub, G_W, Wt, n0, tid);
    cp_commit();
    cp_wait<0>();
    __syncthreads();

    float O[4][4];
#pragma unroll
    for (int n = 0; n < 4; n++)
#pragma unroll
        for (int r = 0; r < 4; r++) O[n][r] = 0.f;

    g64_compute(ub, O, m0, nwoff, lane);

    if (wcomp) {
        // second pass: Wlo into the W region, accumulate (A still resident)
        __syncthreads();
        g64_load_tile(ub, G_W, wvl, n0, tid);
        cp_commit();
        cp_wait<0>();
        __syncthreads();
        g64_compute(ub, O, m0, nwoff, lane);
    }

    // ---- epilogue: f16 packed out ----
    const int r0 = rowBase + m0 + g;
#pragma unroll
    for (int nt = 0; nt < 4; nt++) {
        const int cg = n0 + nwoff + nt * 8 + 2 * q4;
        const float b0 = bias[cg], b1 = bias[cg + 1];
        const float c0 = (O[nt][0] + b0) * scale, c1 = (O[nt][1] + b1) * scale;
        const float c2 = (O[nt][2] + b0) * scale, c3 = (O[nt][3] + b1) * scale;
        const int cu = ((n0 + nwoff) >> 1) + nt * 4 + q4;
        C16[(size_t)r0 * (N / 2) + cu] = pack_f16x2(c0, c1);
        C16[(size_t)(r0 + 8) * (N / 2) + cu] = pack_f16x2(c2, c3);
    }
}

// ======================================================================
// Output projection: grid (4, 256), 256 threads, f32 out.
// ======================================================================
__global__ void __launch_bounds__(256) gemm_o(
        const uint32_t* __restrict__ A16, const uint32_t* __restrict__ Wt,
        const float* __restrict__ bias, float* __restrict__ Cf) {
    extern __shared__ __align__(16) uint32_t sm[];
    const uint32_t ub = (uint32_t)__cvta_generic_to_shared(sm);

    const int tid = threadIdx.x;
    const int wid = tid >> 5;
    const int lane = tid & 31;
    const int g = lane >> 2, q4 = lane & 3;
    const int rowBase = blockIdx.y * 64;
    const int n0 = blockIdx.x * 64;
    const int m0 = (wid & 3) * 16;
    const int nwoff = (wid >> 2) * 32;

    g64_load_tile(ub, G_A, A16, rowBase, tid);
    g64_load_tile(ub, G_W, Wt, n0, tid);
    cp_commit();
    cp_wait<0>();
    __syncthreads();

    float O[4][4];
#pragma unroll
    for (int n = 0; n < 4; n++)
#pragma unroll
        for (int r = 0; r < 4; r++) O[n][r] = 0.f;

    g64_compute(ub, O, m0, nwoff, lane);

    const int r0 = rowBase + m0 + g;
#pragma unroll
    for (int nt = 0; nt < 4; nt++) {
        const int cg = n0 + nwoff + nt * 8 + 2 * q4;
        const float b0 = bias[cg], b1 = bias[cg + 1];
        *(float2*)&Cf[(size_t)r0 * 256 + cg] = make_float2(O[nt][0] + b0, O[nt][1] + b1);
        *(float2*)&Cf[(size_t)(r0 + 8) * 256 + cg] = make_float2(O[nt][2] + b0, O[nt][3] + b1);
    }
}

// ======================================================================
// fp16 flash attention (unchanged, proven).
// ======================================================================
#define AT_VOFF (128*36)
#define AT_BUF  (2*128*36)

__global__ void __launch_bounds__(256) attn16(
        const uint32_t* __restrict__ gq, const uint32_t* __restrict__ gk,
        const uint32_t* __restrict__ gv, uint32_t* __restrict__ ao) {
    extern __shared__ __align__(16) uint32_t sm[];
    const uint32_t ub = (uint32_t)__cvta_generic_to_shared(sm);

    const int tid = threadIdx.x;
    const int wid = tid >> 5;
    const int lane = tid & 31;
    const int g = lane >> 2, q4 = lane & 3;

    const int bh = blockIdx.y;
    const int b = bh >> 2, h = bh & 3;
    const int q0 = blockIdx.x * 128;
    const int m0 = q0 + wid * 16;

    // ones-pad init (V u32 cols 32..35, both buffers)
    {
        const int buf = tid >> 7, row = tid & 127;
        uint4 ones = make_uint4(0x3C003C00u, 0x3C003C00u, 0x3C003C00u, 0x3C003C00u);
        *(uint4*)&sm[buf * AT_BUF + AT_VOFF + row * 36 + 32] = ones;
    }

    // Q fragments (resident; scaled by QSCALE in projection)
    uint32_t Qf[4][4];
    {
        const uint32_t* qp = gq + (size_t)(b*TT + m0 + g) * 128 + h * 32;
#pragma unroll
        for (int kc = 0; kc < 4; kc++) {
            const int du = kc * 8 + q4;
            Qf[kc][0] = qp[du];         Qf[kc][1] = qp[8*128 + du];
            Qf[kc][2] = qp[du + 4];     Qf[kc][3] = qp[8*128 + du + 4];
        }
    }

    const int kn = tid >> 1;
    const int half = (tid & 1) * 16;

    auto load_kv = [&](int it, int bufsel) {
        const uint32_t d0 = ub + (uint32_t)bufsel * AT_BUF * 4;
        const int row = b * TT + it * NB + kn;
        const uint32_t* ks = gk + (size_t)row * 128 + h * 32 + half;
        const uint32_t kd = d0 + (uint32_t)(kn * 36 + half) * 4;
#pragma unroll
        for (int u = 0; u < 4; u++) cp_async16(kd + u * 16, ks + u * 4);
        const uint32_t* vs = gv + (size_t)row * 32 + half;
        const uint32_t vd = d0 + (uint32_t)(AT_VOFF + kn * 36 + half) * 4;
#pragma unroll
        for (int u = 0; u < 4; u++) cp_async16(vd + u * 16, vs + u * 4);
    };

    float O[8][4];
#pragma unroll
    for (int n = 0; n < 8; n++)
#pragma unroll
        for (int r = 0; r < 4; r++) O[n][r] = 0.f;
    float Osum[4] = {0.f, 0.f, 0.f, 0.f};

    const int vLaneRow = (lane & 7) + 8 * ((lane >> 3) & 3);

    load_kv(0, 0);
    cp_commit();

    for (int it = 0; it < TT / NB; it++) {
        if (it + 1 < TT / NB) { load_kv(it + 1, (it + 1) & 1); cp_commit(); cp_wait<1>(); }
        else                  { cp_wait<0>(); }
        __syncthreads();

        const uint32_t bb = ub + (uint32_t)(it & 1) * AT_BUF * 4;
        const uint32_t kBase = bb + (uint32_t)(lane & 7) * 144 + ((lane >> 3) & 3) * 16;
        const uint32_t vBase = bb + AT_VOFF * 4 + (uint32_t)vLaneRow * 144;

#pragma unroll
        for (int sub = 0; sub < 2; sub++) {
#pragma unroll
            for (int hf = 0; hf < 2; hf++) {
                float S[4][4];
#pragma unroll
                for (int jj = 0; jj < 4; jj++) {
#pragma unroll
                    for (int r = 0; r < 4; r++) S[jj][r] = 0.f;
                    const uint32_t rowoff = (uint32_t)(sub*64 + (hf*4 + jj)*8) * 144;
#pragma unroll
                    for (int kcp = 0; kcp < 2; kcp++) {
                        uint32_t Bf[4];
                        ldmatrix_x4(Bf, kBase + rowoff + kcp * 64);
                        mma_f16(S[jj], Qf[2*kcp],     Bf);
                        mma_f16(S[jj], Qf[2*kcp + 1], Bf + 2);
                    }
                }
#pragma unroll
                for (int jj = 0; jj < 4; jj++) {
                    S[jj][0] = ex2f(S[jj][0]);
                    S[jj][1] = ex2f(S[jj][1]);
                    S[jj][2] = ex2f(S[jj][2]);
                    S[jj][3] = ex2f(S[jj][3]);
                }
                uint32_t PhA[4], PhB[4];
                PhA[0] = pack_f16x2(S[0][0], S[0][1]);
                PhA[1] = pack_f16x2(S[0][2], S[0][3]);
                PhA[2] = pack_f16x2(S[1][0], S[1][1]);
                PhA[3] = pack_f16x2(S[1][2], S[1][3]);
                PhB[0] = pack_f16x2(S[2][0], S[2][1]);
                PhB[1] = pack_f16x2(S[2][2], S[2][3]);
                PhB[2] = pack_f16x2(S[3][0], S[3][1]);
                PhB[3] = pack_f16x2(S[3][2], S[3][3]);
                const uint32_t koff = (uint32_t)(sub*64 + hf*32) * 144;
#pragma unroll
                for (int nt = 0; nt < 8; nt++) {
                    uint32_t Vf[4];
                    ldmatrix_x4_t(Vf, vBase + koff + (uint32_t)nt * 16);
                    mma_f16(O[nt], PhA, Vf);
                    mma_f16(O[nt], PhB, Vf + 2);
                }
                {
                    uint32_t Vf[4];
                    ldmatrix_x4_t(Vf, vBase + koff + 8 * 16);
                    mma_f16(Osum, PhA, Vf);
                    mma_f16(Osum, PhB, Vf + 2);
                }
            }
        }
        __syncthreads();
    }

    const float inv0 = 1.f / Osum[0];
    const float inv1 = 1.f / Osum[2];

    uint32_t* dh = ao + (size_t)(b*TT + m0 + g) * 128 + h * 32;
#pragma unroll
    for (int nt = 0; nt < 8; nt++) {
        const int cu = nt * 4 + q4;
        dh[cu]         = pack_f16x2(O[nt][0] * inv0, O[nt][1] * inv0);
        dh[8*128 + cu] = pack_f16x2(O[nt][2] * inv1, O[nt][3] * inv1);
    }
}

// ---------------- launch ----------------
extern "C" void kernel_launch(void* const* d_in, const int* in_sizes, int n_in,
                              void* d_out, int out_size) {
    (void)in_sizes; (void)n_in; (void)out_size;
    const float* query = (const float*)d_in[0];
    const float* key   = (const float*)d_in[1];
    const float* value = (const float*)d_in[2];
    const float* Wq    = (const float*)d_in[3];
    const float* bq    = (const float*)d_in[4];
    const float* Wk    = (const float*)d_in[5];
    const float* bk    = (const float*)d_in[6];
    const float* Wv    = (const float*)d_in[7];
    const float* bv    = (const float*)d_in[8];
    const float* Wo    = (const float*)d_in[9];
    const float* bo    = (const float*)d_in[10];
    float* out = (float*)d_out;

    uint32_t *qi_, *ki_, *vi_, *wq_, *wk_, *wvh_, *wvl_, *wo_;
    uint32_t *q16_, *k16_, *v16_, *ao_;
    cudaGetSymbolAddress((void**)&qi_,  g_qi16);
    cudaGetSymbolAddress((void**)&ki_,  g_ki16);
    cudaGetSymbolAddress((void**)&vi_,  g_vi16);
    cudaGetSymbolAddress((void**)&wq_,  g_wq);
    cudaGetSymbolAddress((void**)&wk_,  g_wk);
    cudaGetSymbolAddress((void**)&wvh_, g_wvh);
    cudaGetSymbolAddress((void**)&wvl_, g_wvl);
    cudaGetSymbolAddress((void**)&wo_,  g_wo);
    cudaGetSymbolAddress((void**)&q16_, g_q16);
    cudaGetSymbolAddress((void**)&k16_, g_k16);
    cudaGetSymbolAddress((void**)&v16_, g_v16);
    cudaGetSymbolAddress((void**)&ao_,  g_ao16);

    const int sm_g  = G_SM * 4;          // 67584
    const int sm_at = 2 * AT_BUF * 4;    // 73728
    cudaFuncSetAttribute(gemm_qkv, cudaFuncAttributeMaxDynamicSharedMemorySize, sm_g);
    cudaFuncSetAttribute(gemm_o,   cudaFuncAttributeMaxDynamicSharedMemorySize, sm_g);
    cudaFuncSetAttribute(attn16,   cudaFuncAttributeMaxDynamicSharedMemorySize, sm_at);

    // 1) prepass (inputs + all weights, one launch)
    prep<<<1440, 256>>>(query, key, value, Wq, Wk, Wv, Wo,
                        qi_, ki_, vi_, wq_, wk_, wvh_, wvl_, wo_);
    // 2) fused Q/K/V projections (barrier-free mainloop, 8 warps/CTA)
    gemm_qkv<<<dim3(4, 256, 3), 256, sm_g>>>(qi_, ki_, vi_, wq_, wk_, wvh_, wvl_,
                                             bq, bk, bv, q16_, k16_, v16_);
    // 3) attention
    attn16<<<dim3(TT / 128, BATCH * NHEAD), 256, sm_at>>>(q16_, k16_, v16_, ao_);
    // 4) output projection (barrier-free mainloop, 8 warps/CTA)
    gemm_o<<<dim3(4, 256), 256, sm_g>>>(ao_, wo_, bo, out);
}

// round 14
// speedup vs baseline: 1.0897x; 1.0059x over previous
#include <cuda_runtime.h>
#include <cuda_fp16.h>
#include <math.h>
#include <stdint.h>

// Problem constants
#define BATCH 16
#define TT    1024
#define DMODEL 256
#define NHEAD 4
#define DKEY  64
#define HDIM  256
#define MROWS (BATCH*TT)   // 16384
#define NB    128          // keys per block

// Q pre-scale: (1/sqrt(64)) * log2(e)  -> scores come out in log2 domain
#define QSCALE 0.1803368801111204f

// ---------------- device scratch ----------------
__device__ uint32_t g_qi16[MROWS * DMODEL / 2];
__device__ uint32_t g_ki16[MROWS * DMODEL / 2];
__device__ uint32_t g_vi16[MROWS * DMODEL / 2];
__device__ uint32_t g_wq [HDIM * DMODEL / 2];
__device__ uint32_t g_wk [HDIM * DMODEL / 2];
__device__ uint32_t g_wvh[DKEY * DMODEL / 2];
__device__ uint32_t g_wvl[DKEY * DMODEL / 2];
__device__ uint32_t g_wo [HDIM * DMODEL / 2];
__device__ uint32_t g_q16[MROWS * HDIM / 2];
__device__ uint32_t g_k16[MROWS * HDIM / 2];
__device__ uint32_t g_v16[MROWS * DKEY / 2];
__device__ uint32_t g_ao16[MROWS * HDIM / 2];

// =============== helpers ===============
__device__ __forceinline__ uint32_t pack_f16x2(float lo, float hi) {
    uint32_t w;
    asm("cvt.rn.f16x2.f32 %0, %1, %2;" : "=r"(w) : "f"(hi), "f"(lo));
    return w;
}
__device__ __forceinline__ float f16_lo_f32(uint32_t w) {
    float f;
    asm("{.reg .b16 l,h; mov.b32 {l,h}, %1; cvt.f32.f16 %0, l;}" : "=f"(f) : "r"(w));
    return f;
}
__device__ __forceinline__ float f16_hi_f32(uint32_t w) {
    float f;
    asm("{.reg .b16 l,h; mov.b32 {l,h}, %1; cvt.f32.f16 %0, h;}" : "=f"(f) : "r"(w));
    return f;
}
__device__ __forceinline__ float ex2f(float x) {
    float y;
    asm("ex2.approx.ftz.f32 %0, %1;" : "=f"(y) : "f"(x));
    return y;
}
__device__ __forceinline__ void mma_f16(float* c, const uint32_t* a, const uint32_t* b) {
    asm volatile(
        "mma.sync.aligned.m16n8k16.row.col.f32.f16.f16.f32 "
        "{%0,%1,%2,%3}, {%4,%5,%6,%7}, {%8,%9}, {%0,%1,%2,%3};"
        : "+f"(c[0]), "+f"(c[1]), "+f"(c[2]), "+f"(c[3])
        : "r"(a[0]), "r"(a[1]), "r"(a[2]), "r"(a[3]), "r"(b[0]), "r"(b[1]));
}
__device__ __forceinline__ void ldmatrix_x4(uint32_t* r, uint32_t addr) {
    asm volatile("ldmatrix.sync.aligned.m8n8.x4.shared.b16 {%0,%1,%2,%3}, [%4];"
        : "=r"(r[0]), "=r"(r[1]), "=r"(r[2]), "=r"(r[3]) : "r"(addr));
}
__device__ __forceinline__ void ldmatrix_x4_t(uint32_t* r, uint32_t addr) {
    asm volatile("ldmatrix.sync.aligned.m8n8.x4.trans.shared.b16 {%0,%1,%2,%3}, [%4];"
        : "=r"(r[0]), "=r"(r[1]), "=r"(r[2]), "=r"(r[3]) : "r"(addr));
}
__device__ __forceinline__ void cp_async16(uint32_t dst, const void* src) {
    asm volatile("cp.async.cg.shared.global [%0], [%1], 16;" :: "r"(dst), "l"(src) : "memory");
}
__device__ __forceinline__ void cp_commit() { asm volatile("cp.async.commit_group;" ::: "memory"); }
template<int W> __device__ __forceinline__ void cp_wait() {
    asm volatile("cp.async.wait_group %0;" :: "n"(W) : "memory");
}

// ======================================================================
// prep: ONE launch. Blocks [0,1024): input f32->f16. Blocks [1024,1440):
// weight transpose/convert (Wq 128 | Wk 128 | Wv 32 (+lo) | Wo 128 blocks).
// ======================================================================
__global__ void prep(const float* __restrict__ q, const float* __restrict__ k,
                     const float* __restrict__ v,
                     const float* __restrict__ Wq, const float* __restrict__ Wk,
                     const float* __restrict__ Wv, const float* __restrict__ Wo,
                     uint32_t* __restrict__ q16, uint32_t* __restrict__ k16,
                     uint32_t* __restrict__ v16,
                     uint32_t* __restrict__ wq, uint32_t* __restrict__ wk,
                     uint32_t* __restrict__ wvh, uint32_t* __restrict__ wvl,
                     uint32_t* __restrict__ wo) {
    const int bx = blockIdx.x;
    if (bx < 1024) {
        const int n = MROWS * DMODEL / 4;
        for (int i = bx * 256 + threadIdx.x; i < n; i += 1024 * 256) {
            float4 a = ((const float4*)q)[i];
            ((uint2*)q16)[i] = make_uint2(pack_f16x2(a.x, a.y), pack_f16x2(a.z, a.w));
            a = ((const float4*)k)[i];
            ((uint2*)k16)[i] = make_uint2(pack_f16x2(a.x, a.y), pack_f16x2(a.z, a.w));
            a = ((const float4*)v)[i];
            ((uint2*)v16)[i] = make_uint2(pack_f16x2(a.x, a.y), pack_f16x2(a.z, a.w));
        }
        return;
    }
    const int wb = bx - 1024;   // 0..415
    int which, setbase;
    if      (wb < 128) { which = 0; setbase = 0;   }
    else if (wb < 256) { which = 1; setbase = 128; }
    else if (wb < 288) { which = 2; setbase = 256; }
    else               { which = 3; setbase = 288; }
    const int N = (which == 2) ? 64 : 256;
    const int t = (wb - setbase) * 256 + threadIdx.x;
    if (t >= N * 128) return;
    const float* W = (which == 0) ? Wq : (which == 1) ? Wk : (which == 2) ? Wv : Wo;
    uint32_t* Wt   = (which == 0) ? wq : (which == 1) ? wk : (which == 2) ? wvh : wo;
    const int n = t % N;
    const int kp = t / N;
    const float w0 = W[(size_t)(2 * kp) * N + n];
    const float w1 = W[(size_t)(2 * kp + 1) * N + n];
    const uint32_t hw = pack_f16x2(w0, w1);
    Wt[(size_t)n * 128 + kp] = hw;
    if (which == 2)
        wvl[(size_t)n * 128 + kp] = pack_f16x2(w0 - f16_lo_f32(hw), w1 - f16_hi_f32(hw));
}

// ======================================================================
// Pipelined GEMM: each CTA owns 4 row-tiles (256 rows) at one 64-col tile.
// W resident once; A tiles stream through 2 cp.async buffers.
// 256 threads = 8 warps (4x2): warp = m16 x n32, O[4][4].
// smem u32: W[64][132] | A0[64][132] | A1[64][132]  (101376 B)
// ======================================================================
#define GR    132
#define G_W   0
#define G_A0  (64*GR)
#define G_A1  (2*64*GR)
#define G_SM  (3*64*GR)                 // 25344 u32 = 101376 B

// load a full 64x256-f16 tile (as [row][128] u32) into smem region (256 thr)
__device__ __forceinline__ void g64_load_tile(uint32_t ub, int region,
                                              const uint32_t* __restrict__ src,
                                              int row0, int tid) {
#pragma unroll
    for (int i = 0; i < 8; i++) {
        const int c = i * 256 + tid;          // 2048 16B-chunks
        const int row = c >> 5, off = (c & 31) * 4;
        cp_async16(ub + (uint32_t)(region + row * GR + off) * 4,
                   src + (size_t)(row0 + row) * 128 + off);
    }
}

// warp computes m16 (at m0, in A region 'areg') x n32 (nwoff in the W tile)
__device__ __forceinline__ void g64_compute(uint32_t ub, int areg, int wreg,
                                            float O[4][4], int m0, int nwoff, int lane) {
    const uint32_t aBase = ub + (uint32_t)areg * 4 +
                           (uint32_t)(m0 + (lane & 15)) * (GR*4) + ((lane >> 4) & 1) * 16;
    const uint32_t bBase = ub + (uint32_t)wreg * 4 +
                           (uint32_t)(nwoff + (lane & 7)) * (GR*4) + ((lane >> 3) & 3) * 16;
#pragma unroll
    for (int kb = 0; kb < 4; kb++) {
#pragma unroll
        for (int kcp = 0; kcp < 2; kcp++) {
            uint32_t Aa[4], Ab[4];
            ldmatrix_x4(Aa, aBase + kb * 128 + (2 * kcp) * 32);
            ldmatrix_x4(Ab, aBase + kb * 128 + (2 * kcp + 1) * 32);
#pragma unroll
            for (int nt = 0; nt < 4; nt++) {
                uint32_t Bf[4];
                ldmatrix_x4(Bf, bBase + (uint32_t)nt * 8 * (GR*4) + kb * 128 + kcp * 64);
                mma_f16(O[nt], Aa, Bf);
                mma_f16(O[nt], Ab, Bf + 2);
            }
        }
    }
}

// ======================================================================
// Fused QKV projection, grid (4, 64, 3), 256 threads.
// z=0: Q (scale=QSCALE); z=1: K; z=2: V (N=64, x==0 only; Whi in W region,
// Wlo resident in A1 region, A single-buffered in A0, 2 compute passes).
// ======================================================================
__global__ void __launch_bounds__(256) gemm_qkv(
        const uint32_t* __restrict__ qi, const uint32_t* __restrict__ ki,
        const uint32_t* __restrict__ vi,
        const uint32_t* __restrict__ wq, const uint32_t* __restrict__ wk,
        const uint32_t* __restrict__ wvh, const uint32_t* __restrict__ wvl,
        const float* __restrict__ bq, const float* __restrict__ bk,
        const float* __restrict__ bv,
        uint32_t* __restrict__ q16, uint32_t* __restrict__ k16,
        uint32_t* __restrict__ v16) {
    const int z = blockIdx.z;
    const bool wcomp = (z == 2);
    if (wcomp && blockIdx.x != 0) return;

    const uint32_t* A16 = (z == 0) ? qi : (z == 1) ? ki : vi;
    const uint32_t* Wt  = (z == 0) ? wq : (z == 1) ? wk : wvh;
    const float* bias   = (z == 0) ? bq : (z == 1) ? bk : bv;
    uint32_t* C16       = (z == 0) ? q16 : (z == 1) ? k16 : v16;
    const int N         = wcomp ? 64 : 256;
    const float scale   = (z == 0) ? QSCALE : 1.0f;

    extern __shared__ __align__(16) uint32_t sm[];
    const uint32_t ub = (uint32_t)__cvta_generic_to_shared(sm);

    const int tid = threadIdx.x;
    const int wid = tid >> 5;
    const int lane = tid & 31;
    const int g = lane >> 2, q4 = lane & 3;
    const int rowStart = blockIdx.y * 256;
    const int n0 = blockIdx.x * 64;
    const int m0 = (wid & 3) * 16;
    const int nwoff = (wid >> 2) * 32;

    if (!wcomp) {
        // ---- pipelined 4-tile path (Q/K) ----
        g64_load_tile(ub, G_W, Wt, n0, tid);
        g64_load_tile(ub, G_A0, A16, rowStart, tid);
        cp_commit();                                   // g0: W + A0
        g64_load_tile(ub, G_A1, A16, rowStart + 64, tid);
        cp_commit();                                   // g1: A1
#pragma unroll
        for (int t = 0; t < 4; t++) {
            if (t == 3) cp_wait<0>(); else cp_wait<1>();
            __syncthreads();
            float O[4][4];
#pragma unroll
            for (int n = 0; n < 4; n++)
#pragma unroll
                for (int r = 0; r < 4; r++) O[n][r] = 0.f;
            const int areg = (t & 1) ? G_A1 : G_A0;
            g64_compute(ub, areg, G_W, O, m0, nwoff, lane);
            __syncthreads();
            if (t + 2 < 4) {
                g64_load_tile(ub, areg, A16, rowStart + (t + 2) * 64, tid);
                cp_commit();
            }
            // epilogue for tile t
            const int r0 = rowStart + t * 64 + m0 + g;
#pragma unroll
            for (int nt = 0; nt < 4; nt++) {
                const int cg = n0 + nwoff + nt * 8 + 2 * q4;
                const float b0 = bias[cg], b1 = bias[cg + 1];
                const float c0 = (O[nt][0] + b0) * scale, c1 = (O[nt][1] + b1) * scale;
                const float c2 = (O[nt][2] + b0) * scale, c3 = (O[nt][3] + b1) * scale;
                const int cu = ((n0 + nwoff) >> 1) + nt * 4 + q4;
                C16[(size_t)r0 * (N / 2) + cu] = pack_f16x2(c0, c1);
                C16[(size_t)(r0 + 8) * (N / 2) + cu] = pack_f16x2(c2, c3);
            }
        }
    } else {
        // ---- V path: Whi + Wlo resident, A single-buffered, 2 passes ----
        g64_load_tile(ub, G_W, Wt, n0, tid);
        g64_load_tile(ub, G_A1, wvl, n0, tid);   // Wlo resident in A1 region
        g64_load_tile(ub, G_A0, A16, rowStart, tid);
        cp_commit();
#pragma unroll
        for (int t = 0; t < 4; t++) {
            cp_wait<0>();
            __syncthreads();
            float O[4][4];
#pragma unroll
            for (int n = 0; n < 4; n++)
#pragma unroll
                for (int r = 0; r < 4; r++) O[n][r] = 0.f;
            g64_compute(ub, G_A0, G_W, O, m0, nwoff, lane);
            g64_compute(ub, G_A0, G_A1, O, m0, nwoff, lane);
            __syncthreads();
            if (t + 1 < 4) {
                g64_load_tile(ub, G_A0, A16, rowStart + (t + 1) * 64, tid);
                cp_commit();
            }
            const int r0 = rowStart + t * 64 + m0 + g;
#pragma unroll
            for (int nt = 0; nt < 4; nt++) {
                const int cg = n0 + nwoff + nt * 8 + 2 * q4;
                const float b0 = bias[cg], b1 = bias[cg + 1];
                const float c0 = O[nt][0] + b0, c1 = O[nt][1] + b1;
                const float c2 = O[nt][2] + b0, c3 = O[nt][3] + b1;
                const int cu = ((n0 + nwoff) >> 1) + nt * 4 + q4;
                C16[(size_t)r0 * (N / 2) + cu] = pack_f16x2(c0, c1);
                C16[(size_t)(r0 + 8) * (N / 2) + cu] = pack_f16x2(c2, c3);
            }
        }
    }
}

// ======================================================================
// Output projection: grid (4, 64), 256 threads, pipelined 4-tile, f32 out.
// ======================================================================
__global__ void __launch_bounds__(256) gemm_o(
        const uint32_t* __restrict__ A16, const uint32_t* __restrict__ Wt,
        const float* __restrict__ bias, float* __restrict__ Cf) {
    extern __shared__ __align__(16) uint32_t sm[];
    const uint32_t ub = (uint32_t)__cvta_generic_to_shared(sm);

    const int tid = threadIdx.x;
    const int wid = tid >> 5;
    const int lane = tid & 31;
    const int g = lane >> 2, q4 = lane & 3;
    const int rowStart = blockIdx.y * 256;
    const int n0 = blockIdx.x * 64;
    const int m0 = (wid & 3) * 16;
    const int nwoff = (wid >> 2) * 32;

    g64_load_tile(ub, G_W, Wt, n0, tid);
    g64_load_tile(ub, G_A0, A16, rowStart, tid);
    cp_commit();
    g64_load_tile(ub, G_A1, A16, rowStart + 64, tid);
    cp_commit();
#pragma unroll
    for (int t = 0; t < 4; t++) {
        if (t == 3) cp_wait<0>(); else cp_wait<1>();
        __syncthreads();
        float O[4][4];
#pragma unroll
        for (int n = 0; n < 4; n++)
#pragma unroll
            for (int r = 0; r < 4; r++) O[n][r] = 0.f;
        const int areg = (t & 1) ? G_A1 : G_A0;
        g64_compute(ub, areg, G_W, O, m0, nwoff, lane);
        __syncthreads();
        if (t + 2 < 4) {
            g64_load_tile(ub, areg, A16, rowStart + (t + 2) * 64, tid);
            cp_commit();
        }
        const int r0 = rowStart + t * 64 + m0 + g;
#pragma unroll
        for (int nt = 0; nt < 4; nt++) {
            const int cg = n0 + nwoff + nt * 8 + 2 * q4;
            const float b0 = bias[cg], b1 = bias[cg + 1];
            *(float2*)&Cf[(size_t)r0 * 256 + cg] = make_float2(O[nt][0] + b0, O[nt][1] + b1);
            *(float2*)&Cf[(size_t)(r0 + 8) * 256 + cg] = make_float2(O[nt][2] + b0, O[nt][3] + b1);
        }
    }
}

// ======================================================================
// fp16 flash attention (unchanged, proven).
// ======================================================================
#define AT_VOFF (128*36)
#define AT_BUF  (2*128*36)

__global__ void __launch_bounds__(256) attn16(
        const uint32_t* __restrict__ gq, const uint32_t* __restrict__ gk,
        const uint32_t* __restrict__ gv, uint32_t* __restrict__ ao) {
    extern __shared__ __align__(16) uint32_t sm[];
    const uint32_t ub = (uint32_t)__cvta_generic_to_shared(sm);

    const int tid = threadIdx.x;
    const int wid = tid >> 5;
    const int lane = tid & 31;
    const int g = lane >> 2, q4 = lane & 3;

    const int bh = blockIdx.y;
    const int b = bh >> 2, h = bh & 3;
    const int q0 = blockIdx.x * 128;
    const int m0 = q0 + wid * 16;

    // ones-pad init (V u32 cols 32..35, both buffers)
    {
        const int buf = tid >> 7, row = tid & 127;
        uint4 ones = make_uint4(0x3C003C00u, 0x3C003C00u, 0x3C003C00u, 0x3C003C00u);
        *(uint4*)&sm[buf * AT_BUF + AT_VOFF + row * 36 + 32] = ones;
    }

    // Q fragments (resident; scaled by QSCALE in projection)
    uint32_t Qf[4][4];
    {
        const uint32_t* qp = gq + (size_t)(b*TT + m0 + g) * 128 + h * 32;
#pragma unroll
        for (int kc = 0; kc < 4; kc++) {
            const int du = kc * 8 + q4;
            Qf[kc][0] = qp[du];         Qf[kc][1] = qp[8*128 + du];
            Qf[kc][2] = qp[du + 4];     Qf[kc][3] = qp[8*128 + du + 4];
        }
    }

    const int kn = tid >> 1;
    const int half = (tid & 1) * 16;

    auto load_kv = [&](int it, int bufsel) {
        const uint32_t d0 = ub + (uint32_t)bufsel * AT_BUF * 4;
        const int row = b * TT + it * NB + kn;
        const uint32_t* ks = gk + (size_t)row * 128 + h * 32 + half;
        const uint32_t kd = d0 + (uint32_t)(kn * 36 + half) * 4;
#pragma unroll
        for (int u = 0; u < 4; u++) cp_async16(kd + u * 16, ks + u * 4);
        const uint32_t* vs = gv + (size_t)row * 32 + half;
        const uint32_t vd = d0 + (uint32_t)(AT_VOFF + kn * 36 + half) * 4;
#pragma unroll
        for (int u = 0; u < 4; u++) cp_async16(vd + u * 16, vs + u * 4);
    };

    float O[8][4];
#pragma unroll
    for (int n = 0; n < 8; n++)
#pragma unroll
        for (int r = 0; r < 4; r++) O[n][r] = 0.f;
    float Osum[4] = {0.f, 0.f, 0.f, 0.f};

    const int vLaneRow = (lane & 7) + 8 * ((lane >> 3) & 3);

    load_kv(0, 0);
    cp_commit();

    for (int it = 0; it < TT / NB; it++) {
        if (it + 1 < TT / NB) { load_kv(it + 1, (it + 1) & 1); cp_commit(); cp_wait<1>(); }
        else                  { cp_wait<0>(); }
        __syncthreads();

        const uint32_t bb = ub + (uint32_t)(it & 1) * AT_BUF * 4;
        const uint32_t kBase = bb + (uint32_t)(lane & 7) * 144 + ((lane >> 3) & 3) * 16;
        const uint32_t vBase = bb + AT_VOFF * 4 + (uint32_t)vLaneRow * 144;

#pragma unroll
        for (int sub = 0; sub < 2; sub++) {
#pragma unroll
            for (int hf = 0; hf < 2; hf++) {
                float S[4][4];
#pragma unroll
                for (int jj = 0; jj < 4; jj++) {
#pragma unroll
                    for (int r = 0; r < 4; r++) S[jj][r] = 0.f;
                    const uint32_t rowoff = (uint32_t)(sub*64 + (hf*4 + jj)*8) * 144;
#pragma unroll
                    for (int kcp = 0; kcp < 2; kcp++) {
                        uint32_t Bf[4];
                        ldmatrix_x4(Bf, kBase + rowoff + kcp * 64);
                        mma_f16(S[jj], Qf[2*kcp],     Bf);
                        mma_f16(S[jj], Qf[2*kcp + 1], Bf + 2);
                    }
                }
#pragma unroll
                for (int jj = 0; jj < 4; jj++) {
                    S[jj][0] = ex2f(S[jj][0]);
                    S[jj][1] = ex2f(S[jj][1]);
                    S[jj][2] = ex2f(S[jj][2]);
                    S[jj][3] = ex2f(S[jj][3]);
                }
                uint32_t PhA[4], PhB[4];
                PhA[0] = pack_f16x2(S[0][0], S[0][1]);
                PhA[1] = pack_f16x2(S[0][2], S[0][3]);
                PhA[2] = pack_f16x2(S[1][0], S[1][1]);
                PhA[3] = pack_f16x2(S[1][2], S[1][3]);
                PhB[0] = pack_f16x2(S[2][0], S[2][1]);
                PhB[1] = pack_f16x2(S[2][2], S[2][3]);
                PhB[2] = pack_f16x2(S[3][0], S[3][1]);
                PhB[3] = pack_f16x2(S[3][2], S[3][3]);
                const uint32_t koff = (uint32_t)(sub*64 + hf*32) * 144;
#pragma unroll
                for (int nt = 0; nt < 8; nt++) {
                    uint32_t Vf[4];
                    ldmatrix_x4_t(Vf, vBase + koff + (uint32_t)nt * 16);
                    mma_f16(O[nt], PhA, Vf);
                    mma_f16(O[nt], PhB, Vf + 2);
                }
                {
                    uint32_t Vf[4];
                    ldmatrix_x4_t(Vf, vBase + koff + 8 * 16);
                    mma_f16(Osum, PhA, Vf);
                    mma_f16(Osum, PhB, Vf + 2);
                }
            }
        }
        __syncthreads();
    }

    const float inv0 = 1.f / Osum[0];
    const float inv1 = 1.f / Osum[2];

    uint32_t* dh = ao + (size_t)(b*TT + m0 + g) * 128 + h * 32;
#pragma unroll
    for (int nt = 0; nt < 8; nt++) {
        const int cu = nt * 4 + q4;
        dh[cu]         = pack_f16x2(O[nt][0] * inv0, O[nt][1] * inv0);
        dh[8*128 + cu] = pack_f16x2(O[nt][2] * inv1, O[nt][3] * inv1);
    }
}

// ---------------- launch ----------------
extern "C" void kernel_launch(void* const* d_in, const int* in_sizes, int n_in,
                              void* d_out, int out_size) {
    (void)in_sizes; (void)n_in; (void)out_size;
    const float* query = (const float*)d_in[0];
    const float* key   = (const float*)d_in[1];
    const float* value = (const float*)d_in[2];
    const float* Wq    = (const float*)d_in[3];
    const float* bq    = (const float*)d_in[4];
    const float* Wk    = (const float*)d_in[5];
    const float* bk    = (const float*)d_in[6];
    const float* Wv    = (const float*)d_in[7];
    const float* bv    = (const float*)d_in[8];
    const float* Wo    = (const float*)d_in[9];
    const float* bo    = (const float*)d_in[10];
    float* out = (float*)d_out;

    uint32_t *qi_, *ki_, *vi_, *wq_, *wk_, *wvh_, *wvl_, *wo_;
    uint32_t *q16_, *k16_, *v16_, *ao_;
    cudaGetSymbolAddress((void**)&qi_,  g_qi16);
    cudaGetSymbolAddress((void**)&ki_,  g_ki16);
    cudaGetSymbolAddress((void**)&vi_,  g_vi16);
    cudaGetSymbolAddress((void**)&wq_,  g_wq);
    cudaGetSymbolAddress((void**)&wk_,  g_wk);
    cudaGetSymbolAddress((void**)&wvh_, g_wvh);
    cudaGetSymbolAddress((void**)&wvl_, g_wvl);
    cudaGetSymbolAddress((void**)&wo_,  g_wo);
    cudaGetSymbolAddress((void**)&q16_, g_q16);
    cudaGetSymbolAddress((void**)&k16_, g_k16);
    cudaGetSymbolAddress((void**)&v16_, g_v16);
    cudaGetSymbolAddress((void**)&ao_,  g_ao16);

    const int sm_g  = G_SM * 4;          // 101376
    const int sm_at = 2 * AT_BUF * 4;    // 73728
    cudaFuncSetAttribute(gemm_qkv, cudaFuncAttributeMaxDynamicSharedMemorySize, sm_g);
    cudaFuncSetAttribute(gemm_o,   cudaFuncAttributeMaxDynamicSharedMemorySize, sm_g);
    cudaFuncSetAttribute(attn16,   cudaFuncAttributeMaxDynamicSharedMemorySize, sm_at);

    // 1) prepass (inputs + all weights, one launch)
    prep<<<1440, 256>>>(query, key, value, Wq, Wk, Wv, Wo,
                        qi_, ki_, vi_, wq_, wk_, wvh_, wvl_, wo_);
    // 2) fused Q/K/V projections (pipelined 4-tile CTAs)
    gemm_qkv<<<dim3(4, 64, 3), 256, sm_g>>>(qi_, ki_, vi_, wq_, wk_, wvh_, wvl_,
                                            bq, bk, bv, q16_, k16_, v16_);
    // 3) attention
    attn16<<<dim3(TT / 128, BATCH * NHEAD), 256, sm_at>>>(q16_, k16_, v16_, ao_);
    // 4) output projection (pipelined 4-tile CTAs, one wave)
    gemm_o<<<dim3(4, 64), 256, sm_g>>>(ao_, wo_, bo, out);
}